// round 4
// baseline (speedup 1.0000x reference)
#include <cuda_runtime.h>
#include <math.h>

#define NB 64
#define NTT 256
#define NE 1024
#define NU 1024
#define KX 2048
#define N3 3072
#define NBLK 128

// ------------------------- device scratch (no allocs allowed) ----------------
__device__ __align__(16) float g_Wcat[KX * N3];                 // packed [C_*;W_*] -> [2048,3072]
__device__ __align__(16) float g_Urz[NU * 2048];                // packed [U_r|U_z] -> [1024,2048]
__device__ __align__(16) float g_G[(size_t)NTT * NB * N3];      // precomputed gate biases [T][B][3072]
__device__ __align__(16) float g_h[NB * NU];
__device__ __align__(16) float g_z[NB * NU];
__device__ __align__(16) float g_a2[NB * NU];                   // h * r
__device__ __align__(16) float g_P[16 * NB * 2048];             // split-K partials

// grid barrier state (monotonic generation -> safe across graph replays)
__device__ unsigned g_cnt = 0;
__device__ unsigned g_gen = 0;

// Generation barrier with a bounded spin: if co-residency were ever violated,
// we terminate (wrong answer) instead of hanging the container. Normal exit is
// microseconds; the cap (~20ms) is never reached in a healthy run.
__device__ __forceinline__ void grid_bar() {
    __syncthreads();
    if (threadIdx.x == 0) {
        unsigned gen = *((volatile unsigned*)&g_gen);
        __threadfence();
        if (atomicAdd(&g_cnt, 1u) == NBLK - 1u) {
            g_cnt = 0;
            __threadfence();
            atomicAdd(&g_gen, 1u);
        } else {
            unsigned spins = 0;
            while (*((volatile unsigned*)&g_gen) == gen) {
                __nanosleep(50);
                if (++spins > 400000u) break;   // safety valve: fail fast, don't hang
            }
        }
        __threadfence();
    }
    __syncthreads();
}

// ------------------------- packing / init -----------------------------------
__global__ void pack_wcat(const float* __restrict__ Wr, const float* __restrict__ Cr,
                          const float* __restrict__ Wz, const float* __restrict__ Cz,
                          const float* __restrict__ Wc, const float* __restrict__ Cc) {
    int stride = gridDim.x * blockDim.x;
    for (int i = blockIdx.x * blockDim.x + threadIdx.x; i < KX * N3; i += stride) {
        int k = i / N3, j = i - k * N3;
        int sel = j >> 10, jj = j & 1023;
        float v;
        if (k < NE) {
            const float* s = (sel == 0) ? Cr : (sel == 1) ? Cz : Cc;
            v = s[k * NU + jj];
        } else {
            const float* s = (sel == 0) ? Wr : (sel == 1) ? Wz : Wc;
            v = s[(k - NE) * NU + jj];
        }
        g_Wcat[i] = v;
    }
}

__global__ void pack_urz_inith(const float* __restrict__ Ur, const float* __restrict__ Uz,
                               const float* __restrict__ h0) {
    int stride = gridDim.x * blockDim.x;
    int i0 = blockIdx.x * blockDim.x + threadIdx.x;
    for (int i = i0; i < NU * 2048; i += stride) {
        int k = i >> 11, j = i & 2047;
        g_Urz[i] = (j < 1024) ? Ur[k * NU + j] : Uz[k * NU + (j - 1024)];
    }
    for (int i = i0; i < NB * NU; i += stride) g_h[i] = h0[i];
}

// ------------------------- precompute GEMM -----------------------------------
// G[t][b][0:1024]=emb@W_r+ctx@C_r, [1024:2048]=...z, [2048:3072]=...cand
__global__ __launch_bounds__(256, 2) void gemm_pre(const float* __restrict__ A) {
    __shared__ __align__(16) float As[16][128];   // transposed A tile
    __shared__ __align__(16) float Bs[16][128];
    const int bn = blockIdx.x * 128;
    const int bm = blockIdx.y * 128;
    const int tid = threadIdx.x;
    const int tx = tid & 15, ty = tid >> 4;
    const int aRow = tid >> 2, aCol = (tid & 3) << 2;
    const int bRow = tid >> 5, bCol = (tid & 31) << 2;

    float acc[8][8];
#pragma unroll
    for (int i = 0; i < 8; i++)
#pragma unroll
        for (int j = 0; j < 8; j++) acc[i][j] = 0.0f;

    float4 pa0, pa1, pb0, pb1;
    {
        const float* Ap = A + (size_t)(bm + aRow) * KX + aCol;
        pa0 = *(const float4*)Ap;
        pa1 = *(const float4*)(Ap + (size_t)64 * KX);
        const float* Bp = g_Wcat + (size_t)bRow * N3 + bn + bCol;
        pb0 = *(const float4*)Bp;
        pb1 = *(const float4*)(Bp + (size_t)8 * N3);
    }
    for (int k0 = 0; k0 < KX; k0 += 16) {
        As[aCol + 0][aRow] = pa0.x; As[aCol + 1][aRow] = pa0.y;
        As[aCol + 2][aRow] = pa0.z; As[aCol + 3][aRow] = pa0.w;
        As[aCol + 0][aRow + 64] = pa1.x; As[aCol + 1][aRow + 64] = pa1.y;
        As[aCol + 2][aRow + 64] = pa1.z; As[aCol + 3][aRow + 64] = pa1.w;
        *(float4*)&Bs[bRow][bCol] = pb0;
        *(float4*)&Bs[bRow + 8][bCol] = pb1;
        __syncthreads();
        if (k0 + 16 < KX) {
            const float* Ap = A + (size_t)(bm + aRow) * KX + (k0 + 16) + aCol;
            pa0 = *(const float4*)Ap;
            pa1 = *(const float4*)(Ap + (size_t)64 * KX);
            const float* Bp = g_Wcat + (size_t)(k0 + 16 + bRow) * N3 + bn + bCol;
            pb0 = *(const float4*)Bp;
            pb1 = *(const float4*)(Bp + (size_t)8 * N3);
        }
#pragma unroll
        for (int kk = 0; kk < 16; kk++) {
            const float4 a0 = *(const float4*)(&As[kk][ty * 8]);
            const float4 a1 = *(const float4*)(&As[kk][ty * 8 + 4]);
            const float4 b0 = *(const float4*)(&Bs[kk][tx * 8]);
            const float4 b1 = *(const float4*)(&Bs[kk][tx * 8 + 4]);
            const float ra[8] = {a0.x, a0.y, a0.z, a0.w, a1.x, a1.y, a1.z, a1.w};
            const float rb[8] = {b0.x, b0.y, b0.z, b0.w, b1.x, b1.y, b1.z, b1.w};
#pragma unroll
            for (int i = 0; i < 8; i++)
#pragma unroll
                for (int j = 0; j < 8; j++) acc[i][j] = fmaf(ra[i], rb[j], acc[i][j]);
        }
        __syncthreads();
    }
#pragma unroll
    for (int i = 0; i < 8; i++) {
        int m = bm + ty * 8 + i;
        int b = m >> 8, t = m & 255;
        float* o = g_G + (size_t)(t * NB + b) * N3 + bn + tx * 8;
        *(float4*)o       = make_float4(acc[i][0], acc[i][1], acc[i][2], acc[i][3]);
        *(float4*)(o + 4) = make_float4(acc[i][4], acc[i][5], acc[i][6], acc[i][7]);
    }
}

// ------------------------- persistent recurrent kernel -----------------------
// 128 CTAs x 256 threads, all co-resident (<=148 SMs). Runs all 256 steps.
__global__ __launch_bounds__(256, 1) void recurrent(const float* __restrict__ U,
                                                    float* __restrict__ out) {
    __shared__ __align__(16) float As[32][64];
    __shared__ __align__(16) float Bs[32][128];
    const int bx = blockIdx.x;
    const int tid = threadIdx.x;
    const int tx = tid & 31, ty = tid >> 5;

    for (int t = 0; t < NTT; t++) {
        // ---- phase A: h @ [U_r|U_z], split-K partials ----
        {
            const int n0 = (bx & 15) * 128;
            const int ks = bx >> 4;                 // 0..7, K chunk of 128
            float acc[8][4] = {};
            for (int kc = 0; kc < 128; kc += 32) {
                const int kb = ks * 128 + kc;
                const int r0 = tid >> 3, c0 = (tid & 7) << 2;
                float4 av0 = *(const float4*)&g_h[r0 * NU + kb + c0];
                float4 av1 = *(const float4*)&g_h[(r0 + 32) * NU + kb + c0];
                As[c0 + 0][r0] = av0.x; As[c0 + 1][r0] = av0.y;
                As[c0 + 2][r0] = av0.z; As[c0 + 3][r0] = av0.w;
                As[c0 + 0][r0 + 32] = av1.x; As[c0 + 1][r0 + 32] = av1.y;
                As[c0 + 2][r0 + 32] = av1.z; As[c0 + 3][r0 + 32] = av1.w;
#pragma unroll
                for (int s = 0; s < 4; s++)
                    *(float4*)&Bs[ty + 8 * s][tx << 2] =
                        *(const float4*)&g_Urz[(size_t)(kb + ty + 8 * s) * 2048 + n0 + (tx << 2)];
                __syncthreads();
#pragma unroll
                for (int kk = 0; kk < 32; kk++) {
                    const float4 a0 = *(const float4*)&As[kk][ty * 8];
                    const float4 a1 = *(const float4*)&As[kk][ty * 8 + 4];
                    const float4 b  = *(const float4*)&Bs[kk][tx * 4];
                    const float ra[8] = {a0.x, a0.y, a0.z, a0.w, a1.x, a1.y, a1.z, a1.w};
                    const float rb[4] = {b.x, b.y, b.z, b.w};
#pragma unroll
                    for (int i = 0; i < 8; i++)
#pragma unroll
                        for (int j = 0; j < 4; j++) acc[i][j] = fmaf(ra[i], rb[j], acc[i][j]);
                }
                __syncthreads();
            }
#pragma unroll
            for (int i = 0; i < 8; i++) {
                int m = ty * 8 + i;
                *(float4*)&g_P[((size_t)ks * 64 + m) * 2048 + n0 + tx * 4] =
                    make_float4(acc[i][0], acc[i][1], acc[i][2], acc[i][3]);
            }
        }
        grid_bar();
        // ---- act_rz: reduce partials, r/z activations, a2 = h*r ----
        {
#pragma unroll
            for (int it = 0; it < 2; it++) {
                int idx = bx * 512 + it * 256 + tid;
                int m = idx >> 10, j = idx & 1023;
                const float* Gp = g_G + (size_t)(t * NB + m) * N3;
                float sr = Gp[j], sz = Gp[1024 + j];
#pragma unroll
                for (int s = 0; s < 8; s++) {
                    const float* Pp = g_P + ((size_t)s * 64 + m) * 2048;
                    sr += Pp[j];
                    sz += Pp[1024 + j];
                }
                float r = fminf(fmaxf(0.2f * sr + 0.5f, 0.0f), 1.0f);
                float z = fminf(fmaxf(0.2f * sz + 0.5f, 0.0f), 1.0f);
                g_z[idx] = z;
                g_a2[idx] = g_h[idx] * r;
            }
        }
        grid_bar();
        // ---- phase B: (h*r) @ U, split-K partials ----
        {
            const int n0 = (bx & 7) * 128;
            const int ks = bx >> 3;                 // 0..15, K chunk of 64
            float acc[8][4] = {};
            for (int kc = 0; kc < 64; kc += 32) {
                const int kb = ks * 64 + kc;
                const int r0 = tid >> 3, c0 = (tid & 7) << 2;
                float4 av0 = *(const float4*)&g_a2[r0 * NU + kb + c0];
                float4 av1 = *(const float4*)&g_a2[(r0 + 32) * NU + kb + c0];
                As[c0 + 0][r0] = av0.x; As[c0 + 1][r0] = av0.y;
                As[c0 + 2][r0] = av0.z; As[c0 + 3][r0] = av0.w;
                As[c0 + 0][r0 + 32] = av1.x; As[c0 + 1][r0 + 32] = av1.y;
                As[c0 + 2][r0 + 32] = av1.z; As[c0 + 3][r0 + 32] = av1.w;
#pragma unroll
                for (int s = 0; s < 4; s++)
                    *(float4*)&Bs[ty + 8 * s][tx << 2] =
                        *(const float4*)&U[(size_t)(kb + ty + 8 * s) * NU + n0 + (tx << 2)];
                __syncthreads();
#pragma unroll
                for (int kk = 0; kk < 32; kk++) {
                    const float4 a0 = *(const float4*)&As[kk][ty * 8];
                    const float4 a1 = *(const float4*)&As[kk][ty * 8 + 4];
                    const float4 b  = *(const float4*)&Bs[kk][tx * 4];
                    const float ra[8] = {a0.x, a0.y, a0.z, a0.w, a1.x, a1.y, a1.z, a1.w};
                    const float rb[4] = {b.x, b.y, b.z, b.w};
#pragma unroll
                    for (int i = 0; i < 8; i++)
#pragma unroll
                        for (int j = 0; j < 4; j++) acc[i][j] = fmaf(ra[i], rb[j], acc[i][j]);
                }
                __syncthreads();
            }
#pragma unroll
            for (int i = 0; i < 8; i++) {
                int m = ty * 8 + i;
                *(float4*)&g_P[((size_t)ks * 64 + m) * 1024 + n0 + tx * 4] =
                    make_float4(acc[i][0], acc[i][1], acc[i][2], acc[i][3]);
            }
        }
        grid_bar();
        // ---- act_h: reduce, tanh, gated update, write output ----
        {
#pragma unroll
            for (int it = 0; it < 2; it++) {
                int idx = bx * 512 + it * 256 + tid;
                int m = idx >> 10, j = idx & 1023;
                float s = g_G[(size_t)(t * NB + m) * N3 + 2048 + j];
#pragma unroll
                for (int ks = 0; ks < 16; ks++) s += g_P[((size_t)ks * 64 + m) * 1024 + j];
                float hc = tanhf(s);
                float z = g_z[idx], h = g_h[idx];
                float hn = (1.0f - z) * h + z * hc;
                g_h[idx] = hn;
                out[((size_t)m * NTT + t) * NU + j] = hn;
            }
        }
        grid_bar();
    }
}

// ------------------------- launch -------------------------------------------
extern "C" void kernel_launch(void* const* d_in, const int* in_sizes, int n_in,
                              void* d_out, int out_size) {
    const float* all = (const float*)d_in[0];
    const float* h0  = (const float*)d_in[1];
    const float* Wr  = (const float*)d_in[2];
    const float* Ur  = (const float*)d_in[3];
    const float* Cr  = (const float*)d_in[4];
    const float* Wz  = (const float*)d_in[5];
    const float* Uz  = (const float*)d_in[6];
    const float* Cz  = (const float*)d_in[7];
    const float* Wc  = (const float*)d_in[8];
    const float* Uc  = (const float*)d_in[9];
    const float* Cc  = (const float*)d_in[10];
    float* out = (float*)d_out;

    pack_wcat<<<4096, 256>>>(Wr, Cr, Wz, Cz, Wc, Cc);
    pack_urz_inith<<<2048, 256>>>(Ur, Uz, h0);
    gemm_pre<<<dim3(24, 128), 256>>>(all);
    recurrent<<<NBLK, 256>>>(Uc, out);
}

// round 6
// speedup vs baseline: 1.2813x; 1.2813x over previous
#include <cuda_runtime.h>
#include <cuda_bf16.h>
#include <math.h>
#include <stdint.h>

#define NB 64
#define NTT 256
#define NU 1024
#define KX 2048
#define N3 3072
#define NBLK 128

// ------------------------- device scratch (no allocs allowed) ----------------
__device__ __align__(16) __nv_bfloat16 g_Ahi[(size_t)16384 * KX];   // 64MB
__device__ __align__(16) __nv_bfloat16 g_Alo[(size_t)16384 * KX];   // 64MB
__device__ __align__(16) __nv_bfloat16 g_Wth[(size_t)N3 * KX];      // W^T hi  [3072][2048]
__device__ __align__(16) __nv_bfloat16 g_Wtl[(size_t)N3 * KX];      // W^T lo
__device__ __align__(16) float g_Urz[NU * 2048];                    // [U_r|U_z] fp32
__device__ __align__(16) float g_G[(size_t)NTT * NB * N3];          // gate biases [T][B][3072]
__device__ __align__(16) float g_h[NB * NU];
__device__ __align__(16) float g_z[NB * NU];
__device__ __align__(16) float g_a2[NB * NU];
__device__ __align__(16) float g_P[16 * NB * 2048];

// grid barrier state (monotonic generation -> safe across graph replays)
__device__ unsigned g_cnt = 0;
__device__ unsigned g_gen = 0;

__device__ __forceinline__ void grid_bar() {
    __syncthreads();
    if (threadIdx.x == 0) {
        unsigned gen = *((volatile unsigned*)&g_gen);
        __threadfence();
        if (atomicAdd(&g_cnt, 1u) == NBLK - 1u) {
            g_cnt = 0;
            __threadfence();
            atomicAdd(&g_gen, 1u);
        } else {
            unsigned spins = 0;
            while (*((volatile unsigned*)&g_gen) == gen) {
                if (++spins > 4096u) __nanosleep(40);      // raw poll first, then sleep
                if (spins > 4000000u) break;               // safety valve: never hang
            }
        }
        __threadfence();
    }
    __syncthreads();
}

// ------------------------- mma.sync helpers (sm_80+ ISA) ---------------------
static __device__ __forceinline__ uint32_t smem_u32(const void* p) {
    uint32_t a;
    asm("{ .reg .u64 t; cvta.to.shared.u64 t, %1; cvt.u32.u64 %0, t; }" : "=r"(a) : "l"(p));
    return a;
}
#define LDSM_X4(r0, r1, r2, r3, a) \
    asm volatile("ldmatrix.sync.aligned.m8n8.x4.shared.b16 {%0,%1,%2,%3}, [%4];" \
                 : "=r"(r0), "=r"(r1), "=r"(r2), "=r"(r3) : "r"(a))
#define MMA_BF16(d, a0, a1, a2, a3, b0, b1) \
    asm volatile("mma.sync.aligned.m16n8k16.row.col.f32.bf16.bf16.f32 " \
                 "{%0,%1,%2,%3}, {%4,%5,%6,%7}, {%8,%9}, {%0,%1,%2,%3};" \
                 : "+f"((d)[0]), "+f"((d)[1]), "+f"((d)[2]), "+f"((d)[3]) \
                 : "r"(a0), "r"(a1), "r"(a2), "r"(a3), "r"(b0), "r"(b1))

// ------------------------- packing / init -----------------------------------
__global__ void pack_a_split(const float* __restrict__ all) {
    size_t n = (size_t)16384 * KX;
    size_t stride = (size_t)gridDim.x * blockDim.x;
    for (size_t i = blockIdx.x * (size_t)blockDim.x + threadIdx.x; i < n; i += stride) {
        float v = all[i];
        __nv_bfloat16 hi = __float2bfloat16(v);
        g_Ahi[i] = hi;
        g_Alo[i] = __float2bfloat16(v - __bfloat162float(hi));
    }
}

__global__ void pack_w_split(const float* __restrict__ Wr, const float* __restrict__ Cr,
                             const float* __restrict__ Wz, const float* __restrict__ Cz,
                             const float* __restrict__ Wc, const float* __restrict__ Cc) {
    size_t n = (size_t)N3 * KX;
    size_t stride = (size_t)gridDim.x * blockDim.x;
    for (size_t i = blockIdx.x * (size_t)blockDim.x + threadIdx.x; i < n; i += stride) {
        int nn = (int)(i >> 11);        // 0..3071 output col
        int k  = (int)(i & 2047);       // 0..2047
        int sel = nn >> 10, j = nn & 1023;
        float v;
        if (k < 1024) {
            const float* s = (sel == 0) ? Cr : (sel == 1) ? Cz : Cc;
            v = s[k * NU + j];
        } else {
            const float* s = (sel == 0) ? Wr : (sel == 1) ? Wz : Wc;
            v = s[(k - 1024) * NU + j];
        }
        __nv_bfloat16 hi = __float2bfloat16(v);
        g_Wth[i] = hi;
        g_Wtl[i] = __float2bfloat16(v - __bfloat162float(hi));
    }
}

__global__ void pack_urz_inith(const float* __restrict__ Ur, const float* __restrict__ Uz,
                               const float* __restrict__ h0) {
    int stride = gridDim.x * blockDim.x;
    int i0 = blockIdx.x * blockDim.x + threadIdx.x;
    for (int i = i0; i < NU * 2048; i += stride) {
        int k = i >> 11, j = i & 2047;
        g_Urz[i] = (j < 1024) ? Ur[k * NU + j] : Uz[k * NU + (j - 1024)];
    }
    for (int i = i0; i < NB * NU; i += stride) g_h[i] = h0[i];
}

// ------------------------- mma.sync precompute GEMM --------------------------
// C[16384,3072] = A[16384,2048] @ W[2048,3072] via bf16 split (hi*hi+hi*lo+lo*hi),
// fp32 accumulation. BM=128 BN=128 BK=32, 8 warps, warp tile 64x32.
#define SPAD 40   // smem row stride in halves (32 data + 8 pad)

__global__ __launch_bounds__(256) void gemm_pre_mma() {
    __shared__ __align__(16) __nv_bfloat16 sAh[128 * SPAD];
    __shared__ __align__(16) __nv_bfloat16 sAl[128 * SPAD];
    __shared__ __align__(16) __nv_bfloat16 sBh[128 * SPAD];
    __shared__ __align__(16) __nv_bfloat16 sBl[128 * SPAD];

    const int tid = threadIdx.x;
    const int wid = tid >> 5, lane = tid & 31;
    const int wm = wid >> 2, wn = wid & 3;         // warp grid 2x4
    const int bn = blockIdx.x, bm = blockIdx.y;

    float acc[4][4][4];
#pragma unroll
    for (int i = 0; i < 4; i++)
#pragma unroll
        for (int j = 0; j < 4; j++)
#pragma unroll
            for (int k = 0; k < 4; k++) acc[i][j][k] = 0.0f;

    const uint32_t aHiB = smem_u32(sAh), aLoB = smem_u32(sAl);
    const uint32_t bHiB = smem_u32(sBh), bLoB = smem_u32(sBl);

    // ldmatrix lane address components
    const int aRowL = wm * 64 + (lane & 15);           // + mi*16
    const int aColL = (lane >> 4) * 8;                 // + ks*16
    const int bRowL = wn * 32 + (lane & 7) + ((lane >> 4) ? 8 : 0);  // + np*16
    const int bColL = ((lane >> 3) & 1) * 8;           // + ks*16

    // global->smem load slots: 2 iters x (slot -> row=slot>>2, col8=(slot&3)*8)
    const int s0 = tid, s1 = tid + 256;
    const int r0 = s0 >> 2, c0 = (s0 & 3) << 3;
    const int r1 = s1 >> 2, c1 = (s1 & 3) << 3;

    for (int kb = 0; kb < KX; kb += 32) {
        __syncthreads();
        {
            size_t ga0 = (size_t)(bm * 128 + r0) * KX + kb + c0;
            size_t ga1 = (size_t)(bm * 128 + r1) * KX + kb + c1;
            *(float4*)&sAh[r0 * SPAD + c0] = *(const float4*)&g_Ahi[ga0];
            *(float4*)&sAh[r1 * SPAD + c1] = *(const float4*)&g_Ahi[ga1];
            *(float4*)&sAl[r0 * SPAD + c0] = *(const float4*)&g_Alo[ga0];
            *(float4*)&sAl[r1 * SPAD + c1] = *(const float4*)&g_Alo[ga1];
            size_t gb0 = (size_t)(bn * 128 + r0) * KX + kb + c0;
            size_t gb1 = (size_t)(bn * 128 + r1) * KX + kb + c1;
            *(float4*)&sBh[r0 * SPAD + c0] = *(const float4*)&g_Wth[gb0];
            *(float4*)&sBh[r1 * SPAD + c1] = *(const float4*)&g_Wth[gb1];
            *(float4*)&sBl[r0 * SPAD + c0] = *(const float4*)&g_Wtl[gb0];
            *(float4*)&sBl[r1 * SPAD + c1] = *(const float4*)&g_Wtl[gb1];
        }
        __syncthreads();

#pragma unroll
        for (int ks = 0; ks < 2; ks++) {
            const int kc = ks * 16;
            uint32_t ah[4][4], al[4][4], bh[4][2], bl[4][2];
#pragma unroll
            for (int mi = 0; mi < 4; mi++) {
                uint32_t ad = aHiB + (uint32_t)(((aRowL + mi * 16) * SPAD + aColL + kc) * 2);
                LDSM_X4(ah[mi][0], ah[mi][1], ah[mi][2], ah[mi][3], ad);
            }
#pragma unroll
            for (int np = 0; np < 2; np++) {
                uint32_t bd = bHiB + (uint32_t)(((bRowL + np * 16) * SPAD + bColL + kc) * 2);
                LDSM_X4(bh[np * 2][0], bh[np * 2][1], bh[np * 2 + 1][0], bh[np * 2 + 1][1], bd);
            }
#pragma unroll
            for (int mi = 0; mi < 4; mi++)
#pragma unroll
                for (int ni = 0; ni < 4; ni++)
                    MMA_BF16(acc[mi][ni], ah[mi][0], ah[mi][1], ah[mi][2], ah[mi][3],
                             bh[ni][0], bh[ni][1]);
#pragma unroll
            for (int np = 0; np < 2; np++) {
                uint32_t bd = bLoB + (uint32_t)(((bRowL + np * 16) * SPAD + bColL + kc) * 2);
                LDSM_X4(bl[np * 2][0], bl[np * 2][1], bl[np * 2 + 1][0], bl[np * 2 + 1][1], bd);
            }
#pragma unroll
            for (int mi = 0; mi < 4; mi++)
#pragma unroll
                for (int ni = 0; ni < 4; ni++)
                    MMA_BF16(acc[mi][ni], ah[mi][0], ah[mi][1], ah[mi][2], ah[mi][3],
                             bl[ni][0], bl[ni][1]);
#pragma unroll
            for (int mi = 0; mi < 4; mi++) {
                uint32_t ad = aLoB + (uint32_t)(((aRowL + mi * 16) * SPAD + aColL + kc) * 2);
                LDSM_X4(al[mi][0], al[mi][1], al[mi][2], al[mi][3], ad);
            }
#pragma unroll
            for (int mi = 0; mi < 4; mi++)
#pragma unroll
                for (int ni = 0; ni < 4; ni++)
                    MMA_BF16(acc[mi][ni], al[mi][0], al[mi][1], al[mi][2], al[mi][3],
                             bh[ni][0], bh[ni][1]);
        }
    }

    // epilogue: write fp32 accumulators to g_G with [T][B] row interleave
#pragma unroll
    for (int mi = 0; mi < 4; mi++) {
        int mA = bm * 128 + wm * 64 + mi * 16 + (lane >> 2);
        int mB = mA + 8;
        int bA = mA >> 8, tA = mA & 255;
        int bB = mB >> 8, tB = mB & 255;
        float* oA = g_G + (size_t)(tA * NB + bA) * N3;
        float* oB = g_G + (size_t)(tB * NB + bB) * N3;
        int colb = bn * 128 + wn * 32 + (lane & 3) * 2;
#pragma unroll
        for (int ni = 0; ni < 4; ni++) {
            int c = colb + ni * 8;
            *(float2*)(oA + c) = make_float2(acc[mi][ni][0], acc[mi][ni][1]);
            *(float2*)(oB + c) = make_float2(acc[mi][ni][2], acc[mi][ni][3]);
        }
    }
}

// ------------------------- persistent recurrent kernel -----------------------
__global__ __launch_bounds__(256, 1) void recurrent(const float* __restrict__ U,
                                                    float* __restrict__ out) {
    __shared__ __align__(16) float As[32][64];
    __shared__ __align__(16) float Bs[32][128];
    const int bx = blockIdx.x;
    const int tid = threadIdx.x;
    const int tx = tid & 31, ty = tid >> 5;

    for (int t = 0; t < NTT; t++) {
        // ---- phase A: h @ [U_r|U_z], split-K partials ----
        {
            const int n0 = (bx & 15) * 128;
            const int ks = bx >> 4;
            float acc[8][4] = {};
            for (int kc = 0; kc < 128; kc += 32) {
                const int kb = ks * 128 + kc;
                const int r0 = tid >> 3, c0 = (tid & 7) << 2;
                float4 av0 = *(const float4*)&g_h[r0 * NU + kb + c0];
                float4 av1 = *(const float4*)&g_h[(r0 + 32) * NU + kb + c0];
                As[c0 + 0][r0] = av0.x; As[c0 + 1][r0] = av0.y;
                As[c0 + 2][r0] = av0.z; As[c0 + 3][r0] = av0.w;
                As[c0 + 0][r0 + 32] = av1.x; As[c0 + 1][r0 + 32] = av1.y;
                As[c0 + 2][r0 + 32] = av1.z; As[c0 + 3][r0 + 32] = av1.w;
#pragma unroll
                for (int s = 0; s < 4; s++)
                    *(float4*)&Bs[ty + 8 * s][tx << 2] =
                        *(const float4*)&g_Urz[(size_t)(kb + ty + 8 * s) * 2048 + n0 + (tx << 2)];
                __syncthreads();
#pragma unroll
                for (int kk = 0; kk < 32; kk++) {
                    const float4 a0 = *(const float4*)&As[kk][ty * 8];
                    const float4 a1 = *(const float4*)&As[kk][ty * 8 + 4];
                    const float4 b  = *(const float4*)&Bs[kk][tx * 4];
                    const float ra[8] = {a0.x, a0.y, a0.z, a0.w, a1.x, a1.y, a1.z, a1.w};
                    const float rb[4] = {b.x, b.y, b.z, b.w};
#pragma unroll
                    for (int i = 0; i < 8; i++)
#pragma unroll
                        for (int j = 0; j < 4; j++) acc[i][j] = fmaf(ra[i], rb[j], acc[i][j]);
                }
                __syncthreads();
            }
#pragma unroll
            for (int i = 0; i < 8; i++) {
                int m = ty * 8 + i;
                *(float4*)&g_P[((size_t)ks * 64 + m) * 2048 + n0 + tx * 4] =
                    make_float4(acc[i][0], acc[i][1], acc[i][2], acc[i][3]);
            }
        }
        grid_bar();
        // ---- act_rz ----
        {
#pragma unroll
            for (int it = 0; it < 2; it++) {
                int idx = bx * 512 + it * 256 + tid;
                int m = idx >> 10, j = idx & 1023;
                const float* Gp = g_G + (size_t)(t * NB + m) * N3;
                float sr = Gp[j], sz = Gp[1024 + j];
#pragma unroll
                for (int s = 0; s < 8; s++) {
                    const float* Pp = g_P + ((size_t)s * 64 + m) * 2048;
                    sr += Pp[j];
                    sz += Pp[1024 + j];
                }
                float r = fminf(fmaxf(0.2f * sr + 0.5f, 0.0f), 1.0f);
                float z = fminf(fmaxf(0.2f * sz + 0.5f, 0.0f), 1.0f);
                g_z[idx] = z;
                g_a2[idx] = g_h[idx] * r;
            }
        }
        grid_bar();
        // ---- phase B: (h*r) @ U ----
        {
            const int n0 = (bx & 7) * 128;
            const int ks = bx >> 3;
            float acc[8][4] = {};
            for (int kc = 0; kc < 64; kc += 32) {
                const int kb = ks * 64 + kc;
                const int r0 = tid >> 3, c0 = (tid & 7) << 2;
                float4 av0 = *(const float4*)&g_a2[r0 * NU + kb + c0];
                float4 av1 = *(const float4*)&g_a2[(r0 + 32) * NU + kb + c0];
                As[c0 + 0][r0] = av0.x; As[c0 + 1][r0] = av0.y;
                As[c0 + 2][r0] = av0.z; As[c0 + 3][r0] = av0.w;
                As[c0 + 0][r0 + 32] = av1.x; As[c0 + 1][r0 + 32] = av1.y;
                As[c0 + 2][r0 + 32] = av1.z; As[c0 + 3][r0 + 32] = av1.w;
#pragma unroll
                for (int s = 0; s < 4; s++)
                    *(float4*)&Bs[ty + 8 * s][tx << 2] =
                        *(const float4*)&U[(size_t)(kb + ty + 8 * s) * NU + n0 + (tx << 2)];
                __syncthreads();
#pragma unroll
                for (int kk = 0; kk < 32; kk++) {
                    const float4 a0 = *(const float4*)&As[kk][ty * 8];
                    const float4 a1 = *(const float4*)&As[kk][ty * 8 + 4];
                    const float4 b  = *(const float4*)&Bs[kk][tx * 4];
                    const float ra[8] = {a0.x, a0.y, a0.z, a0.w, a1.x, a1.y, a1.z, a1.w};
                    const float rb[4] = {b.x, b.y, b.z, b.w};
#pragma unroll
                    for (int i = 0; i < 8; i++)
#pragma unroll
                        for (int j = 0; j < 4; j++) acc[i][j] = fmaf(ra[i], rb[j], acc[i][j]);
                }
                __syncthreads();
            }
#pragma unroll
            for (int i = 0; i < 8; i++) {
                int m = ty * 8 + i;
                *(float4*)&g_P[((size_t)ks * 64 + m) * 1024 + n0 + tx * 4] =
                    make_float4(acc[i][0], acc[i][1], acc[i][2], acc[i][3]);
            }
        }
        grid_bar();
        // ---- act_h ----
        {
#pragma unroll
            for (int it = 0; it < 2; it++) {
                int idx = bx * 512 + it * 256 + tid;
                int m = idx >> 10, j = idx & 1023;
                float s = g_G[(size_t)(t * NB + m) * N3 + 2048 + j];
#pragma unroll
                for (int ks = 0; ks < 16; ks++) s += g_P[((size_t)ks * 64 + m) * 1024 + j];
                float hc = tanhf(s);
                float z = g_z[idx], h = g_h[idx];
                float hn = (1.0f - z) * h + z * hc;
                g_h[idx] = hn;
                out[((size_t)m * NTT + t) * NU + j] = hn;
            }
        }
        grid_bar();
    }
}

// ------------------------- launch -------------------------------------------
extern "C" void kernel_launch(void* const* d_in, const int* in_sizes, int n_in,
                              void* d_out, int out_size) {
    const float* all = (const float*)d_in[0];
    const float* h0  = (const float*)d_in[1];
    const float* Wr  = (const float*)d_in[2];
    const float* Ur  = (const float*)d_in[3];
    const float* Cr  = (const float*)d_in[4];
    const float* Wz  = (const float*)d_in[5];
    const float* Uz  = (const float*)d_in[6];
    const float* Cz  = (const float*)d_in[7];
    const float* Wc  = (const float*)d_in[8];
    const float* Uc  = (const float*)d_in[9];
    const float* Cc  = (const float*)d_in[10];
    float* out = (float*)d_out;

    pack_a_split<<<4096, 256>>>(all);
    pack_w_split<<<2048, 256>>>(Wr, Cr, Wz, Cz, Wc, Cc);
    pack_urz_inith<<<2048, 256>>>(Ur, Uz, h0);
    gemm_pre_mma<<<dim3(24, 128), 256>>>();
    recurrent<<<NBLK, 256>>>(Uc, out);
}

// round 7
// speedup vs baseline: 1.5019x; 1.1722x over previous
#include <cuda_runtime.h>
#include <cuda_bf16.h>
#include <math.h>
#include <stdint.h>

#define NB 64
#define NTT 256
#define NU 1024
#define KX 2048
#define N3 3072
#define NBLK 128
#define SROW 136            // halves per staged row (128 + 8 pad)
#define SBUFH (64 * SROW)   // halves per (buf,split) tile

// ------------------------- device scratch (no allocs allowed) ----------------
__device__ __align__(16) __nv_bfloat16 g_Ahi[(size_t)16384 * KX];
__device__ __align__(16) __nv_bfloat16 g_Alo[(size_t)16384 * KX];
__device__ __align__(16) __nv_bfloat16 g_Wth[(size_t)N3 * KX];
__device__ __align__(16) __nv_bfloat16 g_Wtl[(size_t)N3 * KX];
__device__ __align__(16) float g_G[(size_t)NTT * NB * N3];
__device__ __align__(16) uint4 g_UrzF[256 * 64 * 32];   // frag-packed [U_r|U_z] hi/lo, 8MB
__device__ __align__(16) uint4 g_UcF[128 * 64 * 32];    // frag-packed U, 4MB
__device__ __align__(16) float g_h[NB * NU];
__device__ __align__(16) __nv_bfloat16 g_hh[NB * NU];
__device__ __align__(16) __nv_bfloat16 g_hl[NB * NU];
__device__ __align__(16) float g_z[NB * NU];
__device__ __align__(16) __nv_bfloat16 g_a2h[NB * NU];
__device__ __align__(16) __nv_bfloat16 g_a2l[NB * NU];

// grid barrier state (monotonic generation -> safe across graph replays)
__device__ unsigned g_cnt = 0;
__device__ unsigned g_gen = 0;

__device__ __forceinline__ void grid_bar() {
    __syncthreads();
    if (threadIdx.x == 0) {
        unsigned gen = *((volatile unsigned*)&g_gen);
        __threadfence();
        if (atomicAdd(&g_cnt, 1u) == NBLK - 1u) {
            g_cnt = 0;
            __threadfence();
            atomicAdd(&g_gen, 1u);
        } else {
            unsigned spins = 0;
            while (*((volatile unsigned*)&g_gen) == gen) {
                if (++spins > 4096u) __nanosleep(40);
                if (spins > 4000000u) break;   // safety valve: never hang
            }
        }
        __threadfence();
    }
    __syncthreads();
}

// ------------------------- mma.sync helpers (sm_80+ ISA) ---------------------
static __device__ __forceinline__ uint32_t smem_u32(const void* p) {
    uint32_t a;
    asm("{ .reg .u64 t; cvta.to.shared.u64 t, %1; cvt.u32.u64 %0, t; }" : "=r"(a) : "l"(p));
    return a;
}
#define LDSM_X4(r0, r1, r2, r3, a) \
    asm volatile("ldmatrix.sync.aligned.m8n8.x4.shared.b16 {%0,%1,%2,%3}, [%4];" \
                 : "=r"(r0), "=r"(r1), "=r"(r2), "=r"(r3) : "r"(a))
#define MMA_BF16(d, a0, a1, a2, a3, b0, b1) \
    asm volatile("mma.sync.aligned.m16n8k16.row.col.f32.bf16.bf16.f32 " \
                 "{%0,%1,%2,%3}, {%4,%5,%6,%7}, {%8,%9}, {%0,%1,%2,%3};" \
                 : "+f"((d)[0]), "+f"((d)[1]), "+f"((d)[2]), "+f"((d)[3]) \
                 : "r"(a0), "r"(a1), "r"(a2), "r"(a3), "r"(b0), "r"(b1))

static __device__ __forceinline__ uint32_t pack2hi(float x, float y) {
    __nv_bfloat162 v = {__float2bfloat16(x), __float2bfloat16(y)};
    return *(uint32_t*)&v;
}
static __device__ __forceinline__ uint32_t pack2lo(float x, float y) {
    float hx = __bfloat162float(__float2bfloat16(x));
    float hy = __bfloat162float(__float2bfloat16(y));
    __nv_bfloat162 v = {__float2bfloat16(x - hx), __float2bfloat16(y - hy)};
    return *(uint32_t*)&v;
}
static __device__ __forceinline__ float hsig(float x) {
    return fminf(fmaxf(0.2f * x + 0.5f, 0.0f), 1.0f);
}

// ------------------------- packing / init -----------------------------------
__global__ void pack_a_split(const float* __restrict__ all) {
    size_t n = (size_t)16384 * KX;
    size_t stride = (size_t)gridDim.x * blockDim.x;
    for (size_t i = blockIdx.x * (size_t)blockDim.x + threadIdx.x; i < n; i += stride) {
        float v = all[i];
        __nv_bfloat16 hi = __float2bfloat16(v);
        g_Ahi[i] = hi;
        g_Alo[i] = __float2bfloat16(v - __bfloat162float(hi));
    }
}

__global__ void pack_w_split(const float* __restrict__ Wr, const float* __restrict__ Cr,
                             const float* __restrict__ Wz, const float* __restrict__ Cz,
                             const float* __restrict__ Wc, const float* __restrict__ Cc) {
    size_t n = (size_t)N3 * KX;
    size_t stride = (size_t)gridDim.x * blockDim.x;
    for (size_t i = blockIdx.x * (size_t)blockDim.x + threadIdx.x; i < n; i += stride) {
        int nn = (int)(i >> 11);
        int k  = (int)(i & 2047);
        int sel = nn >> 10, j = nn & 1023;
        float v;
        if (k < 1024) {
            const float* s = (sel == 0) ? Cr : (sel == 1) ? Cz : Cc;
            v = s[k * NU + j];
        } else {
            const float* s = (sel == 0) ? Wr : (sel == 1) ? Wz : Wc;
            v = s[(k - 1024) * NU + j];
        }
        __nv_bfloat16 hi = __float2bfloat16(v);
        g_Wth[i] = hi;
        g_Wtl[i] = __float2bfloat16(v - __bfloat162float(hi));
    }
}

// frag-major packing of [U_r | U_z]: layout ((nt*64 + kc)*32 + lane) -> {b0h,b1h,b0l,b1l}
__global__ void pack_UrzF(const float* __restrict__ Ur, const float* __restrict__ Uz) {
    int fid = blockIdx.x * blockDim.x + threadIdx.x;   // 524288
    int nt = fid >> 11, kc = (fid >> 5) & 63, lane = fid & 31;
    int n = nt * 8 + (lane >> 2);
    int k0 = kc * 16 + (lane & 3) * 2;
    const float* src = (n < 1024) ? Ur : Uz;
    int nn = n & 1023;
    float v00 = src[(k0 + 0) * NU + nn], v01 = src[(k0 + 1) * NU + nn];
    float v10 = src[(k0 + 8) * NU + nn], v11 = src[(k0 + 9) * NU + nn];
    g_UrzF[fid] = make_uint4(pack2hi(v00, v01), pack2hi(v10, v11),
                             pack2lo(v00, v01), pack2lo(v10, v11));
}

__global__ void pack_UcF(const float* __restrict__ Uc) {
    int fid = blockIdx.x * blockDim.x + threadIdx.x;   // 262144
    int nt = fid >> 11, kc = (fid >> 5) & 63, lane = fid & 31;
    int n = nt * 8 + (lane >> 2);
    int k0 = kc * 16 + (lane & 3) * 2;
    float v00 = Uc[(k0 + 0) * NU + n], v01 = Uc[(k0 + 1) * NU + n];
    float v10 = Uc[(k0 + 8) * NU + n], v11 = Uc[(k0 + 9) * NU + n];
    g_UcF[fid] = make_uint4(pack2hi(v00, v01), pack2hi(v10, v11),
                            pack2lo(v00, v01), pack2lo(v10, v11));
}

__global__ void pack_h_split(const float* __restrict__ h0) {
    int i = blockIdx.x * blockDim.x + threadIdx.x;     // 65536
    float v = h0[i];
    g_h[i] = v;
    __nv_bfloat16 hi = __float2bfloat16(v);
    g_hh[i] = hi;
    g_hl[i] = __float2bfloat16(v - __bfloat162float(hi));
}

// ------------------------- mma.sync precompute GEMM (unchanged, passing) -----
#define SPAD 40

__global__ __launch_bounds__(256) void gemm_pre_mma() {
    __shared__ __align__(16) __nv_bfloat16 sAh[128 * SPAD];
    __shared__ __align__(16) __nv_bfloat16 sAl[128 * SPAD];
    __shared__ __align__(16) __nv_bfloat16 sBh[128 * SPAD];
    __shared__ __align__(16) __nv_bfloat16 sBl[128 * SPAD];

    const int tid = threadIdx.x;
    const int wid = tid >> 5, lane = tid & 31;
    const int wm = wid >> 2, wn = wid & 3;
    const int bn = blockIdx.x, bm = blockIdx.y;

    float acc[4][4][4];
#pragma unroll
    for (int i = 0; i < 4; i++)
#pragma unroll
        for (int j = 0; j < 4; j++)
#pragma unroll
            for (int k = 0; k < 4; k++) acc[i][j][k] = 0.0f;

    const uint32_t aHiB = smem_u32(sAh), aLoB = smem_u32(sAl);
    const uint32_t bHiB = smem_u32(sBh), bLoB = smem_u32(sBl);

    const int aRowL = wm * 64 + (lane & 15);
    const int aColL = (lane >> 4) * 8;
    const int bRowL = wn * 32 + (lane & 7) + ((lane >> 4) ? 8 : 0);
    const int bColL = ((lane >> 3) & 1) * 8;

    const int s0 = tid, s1 = tid + 256;
    const int r0 = s0 >> 2, c0 = (s0 & 3) << 3;
    const int r1 = s1 >> 2, c1 = (s1 & 3) << 3;

    for (int kb = 0; kb < KX; kb += 32) {
        __syncthreads();
        {
            size_t ga0 = (size_t)(bm * 128 + r0) * KX + kb + c0;
            size_t ga1 = (size_t)(bm * 128 + r1) * KX + kb + c1;
            *(float4*)&sAh[r0 * SPAD + c0] = *(const float4*)&g_Ahi[ga0];
            *(float4*)&sAh[r1 * SPAD + c1] = *(const float4*)&g_Ahi[ga1];
            *(float4*)&sAl[r0 * SPAD + c0] = *(const float4*)&g_Alo[ga0];
            *(float4*)&sAl[r1 * SPAD + c1] = *(const float4*)&g_Alo[ga1];
            size_t gb0 = (size_t)(bn * 128 + r0) * KX + kb + c0;
            size_t gb1 = (size_t)(bn * 128 + r1) * KX + kb + c1;
            *(float4*)&sBh[r0 * SPAD + c0] = *(const float4*)&g_Wth[gb0];
            *(float4*)&sBh[r1 * SPAD + c1] = *(const float4*)&g_Wth[gb1];
            *(float4*)&sBl[r0 * SPAD + c0] = *(const float4*)&g_Wtl[gb0];
            *(float4*)&sBl[r1 * SPAD + c1] = *(const float4*)&g_Wtl[gb1];
        }
        __syncthreads();

#pragma unroll
        for (int ks = 0; ks < 2; ks++) {
            const int kc = ks * 16;
            uint32_t ah[4][4], al[4][4], bh[4][2], bl[4][2];
#pragma unroll
            for (int mi = 0; mi < 4; mi++) {
                uint32_t ad = aHiB + (uint32_t)(((aRowL + mi * 16) * SPAD + aColL + kc) * 2);
                LDSM_X4(ah[mi][0], ah[mi][1], ah[mi][2], ah[mi][3], ad);
            }
#pragma unroll
            for (int np = 0; np < 2; np++) {
                uint32_t bd = bHiB + (uint32_t)(((bRowL + np * 16) * SPAD + bColL + kc) * 2);
                LDSM_X4(bh[np * 2][0], bh[np * 2][1], bh[np * 2 + 1][0], bh[np * 2 + 1][1], bd);
            }
#pragma unroll
            for (int mi = 0; mi < 4; mi++)
#pragma unroll
                for (int ni = 0; ni < 4; ni++)
                    MMA_BF16(acc[mi][ni], ah[mi][0], ah[mi][1], ah[mi][2], ah[mi][3],
                             bh[ni][0], bh[ni][1]);
#pragma unroll
            for (int np = 0; np < 2; np++) {
                uint32_t bd = bLoB + (uint32_t)(((bRowL + np * 16) * SPAD + bColL + kc) * 2);
                LDSM_X4(bl[np * 2][0], bl[np * 2][1], bl[np * 2 + 1][0], bl[np * 2 + 1][1], bd);
            }
#pragma unroll
            for (int mi = 0; mi < 4; mi++)
#pragma unroll
                for (int ni = 0; ni < 4; ni++)
                    MMA_BF16(acc[mi][ni], ah[mi][0], ah[mi][1], ah[mi][2], ah[mi][3],
                             bl[ni][0], bl[ni][1]);
#pragma unroll
            for (int mi = 0; mi < 4; mi++) {
                uint32_t ad = aLoB + (uint32_t)(((aRowL + mi * 16) * SPAD + aColL + kc) * 2);
                LDSM_X4(al[mi][0], al[mi][1], al[mi][2], al[mi][3], ad);
            }
#pragma unroll
            for (int mi = 0; mi < 4; mi++)
#pragma unroll
                for (int ni = 0; ni < 4; ni++)
                    MMA_BF16(acc[mi][ni], al[mi][0], al[mi][1], al[mi][2], al[mi][3],
                             bh[ni][0], bh[ni][1]);
        }
    }

#pragma unroll
    for (int mi = 0; mi < 4; mi++) {
        int mA = bm * 128 + wm * 64 + mi * 16 + (lane >> 2);
        int mB = mA + 8;
        int bA = mA >> 8, tA = mA & 255;
        int bB = mB >> 8, tB = mB & 255;
        float* oA = g_G + (size_t)(tA * NB + bA) * N3;
        float* oB = g_G + (size_t)(tB * NB + bB) * N3;
        int colb = bn * 128 + wn * 32 + (lane & 3) * 2;
#pragma unroll
        for (int ni = 0; ni < 4; ni++) {
            int c = colb + ni * 8;
            *(float2*)(oA + c) = make_float2(acc[mi][ni][0], acc[mi][ni][1]);
            *(float2*)(oB + c) = make_float2(acc[mi][ni][2], acc[mi][ni][3]);
        }
    }
}

// ------------------------- persistent recurrent kernel (tensorized) ----------
// 128 CTAs x 256 threads. Phase A: CTA owns 16 gate cols (full K); fused act_rz.
// Phase B: CTA owns 8 output cols (K split 2x in-CTA); fused act_h. 2 barriers/step.
static __device__ __forceinline__ void stage_chunk(__nv_bfloat16* smh, __nv_bfloat16* sml,
                                                   const __nv_bfloat16* gh,
                                                   const __nv_bfloat16* gl,
                                                   int kb, int tid) {
#pragma unroll
    for (int it = 0; it < 4; it++) {
        int slot = it * 256 + tid;
        int row = slot >> 4, grp = slot & 15;
        *(uint4*)(smh + row * SROW + grp * 8) = *(const uint4*)(gh + row * NU + kb + grp * 8);
        *(uint4*)(sml + row * SROW + grp * 8) = *(const uint4*)(gl + row * NU + kb + grp * 8);
    }
}

__global__ __launch_bounds__(256, 1) void recurrent(float* __restrict__ out) {
    extern __shared__ __align__(16) char smraw[];
    __nv_bfloat16* sm = (__nv_bfloat16*)smraw;
    float* red = (float*)(smraw + 4 * SBUFH * 2);      // 4 tiles * SBUFH halves * 2B
    const int bx = blockIdx.x;
    const int tid = threadIdx.x;
    const int wid = tid >> 5, lane = tid & 31;
    const int wm = wid >> 1, ws = wid & 1;             // phase A: ws=n8 tile; phase B: ws=k half

    const int lrow = lane & 15, lcol = (lane >> 4) * 8;
    const int erow = wm * 16 + (lane >> 2);            // epilogue row (c0/c1)
    const int ecol2 = (lane & 3) * 2;

    for (int t = 0; t < NTT; t++) {
        // ================= phase A: h @ [U_r|U_z], cols bx*16..+16, fused act_rz ====
        {
            float acc[4] = {0.f, 0.f, 0.f, 0.f};
            const uint4* bfr = g_UrzF + ((size_t)(bx * 2 + ws) * 64) * 32 + lane;
            stage_chunk(sm, sm + SBUFH, g_hh, g_hl, 0, tid);
            __syncthreads();
            for (int i = 0; i < 8; i++) {
                if (i < 7) {
                    int nb = (i + 1) & 1;
                    stage_chunk(sm + nb * 2 * SBUFH, sm + (nb * 2 + 1) * SBUFH,
                                g_hh, g_hl, (i + 1) * 128, tid);
                }
                const int cb = i & 1;
                uint32_t baseH = smem_u32(sm + cb * 2 * SBUFH + (wm * 16 + lrow) * SROW + lcol);
                uint32_t baseL = smem_u32(sm + (cb * 2 + 1) * SBUFH + (wm * 16 + lrow) * SROW + lcol);
#pragma unroll
                for (int kc = 0; kc < 8; kc++) {
                    uint32_t a0, a1, a2, a3, l0, l1, l2, l3;
                    LDSM_X4(a0, a1, a2, a3, baseH + kc * 32);
                    LDSM_X4(l0, l1, l2, l3, baseL + kc * 32);
                    uint4 bv = bfr[(i * 8 + kc) * 32];
                    MMA_BF16(acc, a0, a1, a2, a3, bv.x, bv.y);
                    MMA_BF16(acc, a0, a1, a2, a3, bv.z, bv.w);
                    MMA_BF16(acc, l0, l1, l2, l3, bv.x, bv.y);
                }
                __syncthreads();
            }
            // fused epilogue
            const int colg = bx * 16 + ws * 8 + ecol2;     // global gate col (0..2047)
            float s00 = acc[0] + g_G[((size_t)t * NB + erow) * N3 + colg];
            float s01 = acc[1] + g_G[((size_t)t * NB + erow) * N3 + colg + 1];
            float s10 = acc[2] + g_G[((size_t)t * NB + erow + 8) * N3 + colg];
            float s11 = acc[3] + g_G[((size_t)t * NB + erow + 8) * N3 + colg + 1];
            if (bx < 64) {                                  // r gate -> a2 = h*r
                float2 h0 = *(const float2*)&g_h[erow * NU + colg];
                float2 h1 = *(const float2*)&g_h[(erow + 8) * NU + colg];
                float a0 = h0.x * hsig(s00), a1 = h0.y * hsig(s01);
                float a2v = h1.x * hsig(s10), a3v = h1.y * hsig(s11);
                *(uint32_t*)&g_a2h[erow * NU + colg] = pack2hi(a0, a1);
                *(uint32_t*)&g_a2l[erow * NU + colg] = pack2lo(a0, a1);
                *(uint32_t*)&g_a2h[(erow + 8) * NU + colg] = pack2hi(a2v, a3v);
                *(uint32_t*)&g_a2l[(erow + 8) * NU + colg] = pack2lo(a2v, a3v);
            } else {                                        // z gate
                int j = colg - 1024;
                *(float2*)&g_z[erow * NU + j] = make_float2(hsig(s00), hsig(s01));
                *(float2*)&g_z[(erow + 8) * NU + j] = make_float2(hsig(s10), hsig(s11));
            }
        }
        grid_bar();
        // ================= phase B: (h*r) @ U, cols bx*8..+8, fused act_h ==========
        {
            float acc[4] = {0.f, 0.f, 0.f, 0.f};
            const uint4* bfr = g_UcF + ((size_t)bx * 64) * 32 + lane;
            for (int r = 0; r < 4; r++) {
                __syncthreads();
                stage_chunk(sm, sm + SBUFH, g_a2h, g_a2l, r * 128, tid);
                stage_chunk(sm + 2 * SBUFH, sm + 3 * SBUFH, g_a2h, g_a2l, 512 + r * 128, tid);
                __syncthreads();
                uint32_t baseH = smem_u32(sm + ws * 2 * SBUFH + (wm * 16 + lrow) * SROW + lcol);
                uint32_t baseL = smem_u32(sm + (ws * 2 + 1) * SBUFH + (wm * 16 + lrow) * SROW + lcol);
#pragma unroll
                for (int kc = 0; kc < 8; kc++) {
                    uint32_t a0, a1, a2, a3, l0, l1, l2, l3;
                    LDSM_X4(a0, a1, a2, a3, baseH + kc * 32);
                    LDSM_X4(l0, l1, l2, l3, baseL + kc * 32);
                    uint4 bv = bfr[(ws * 32 + r * 8 + kc) * 32];
                    MMA_BF16(acc, a0, a1, a2, a3, bv.x, bv.y);
                    MMA_BF16(acc, a0, a1, a2, a3, bv.z, bv.w);
                    MMA_BF16(acc, l0, l1, l2, l3, bv.x, bv.y);
                }
            }
            // k-half partials -> smem
            *(float2*)&red[((ws * 64) + erow) * 8 + ecol2] = make_float2(acc[0], acc[1]);
            *(float2*)&red[((ws * 64) + erow + 8) * 8 + ecol2] = make_float2(acc[2], acc[3]);
            __syncthreads();
            // fused act_h: 512 outputs, 2 per thread
#pragma unroll
            for (int o = tid; o < 512; o += 256) {
                int b = o >> 3, jj = o & 7;
                int j = bx * 8 + jj;
                float s = red[b * 8 + jj] + red[(64 + b) * 8 + jj]
                        + g_G[((size_t)t * NB + b) * N3 + 2048 + j];
                float hc = tanhf(s);
                float z = g_z[b * NU + j], h = g_h[b * NU + j];
                float hn = (1.0f - z) * h + z * hc;
                g_h[b * NU + j] = hn;
                __nv_bfloat16 hh = __float2bfloat16(hn);
                g_hh[b * NU + j] = hh;
                g_hl[b * NU + j] = __float2bfloat16(hn - __bfloat162float(hh));
                out[((size_t)b * NTT + t) * NU + j] = hn;
            }
        }
        grid_bar();
    }
}

// ------------------------- launch -------------------------------------------
#define REC_SMEM (4 * SBUFH * 2 + 4096)

extern "C" void kernel_launch(void* const* d_in, const int* in_sizes, int n_in,
                              void* d_out, int out_size) {
    const float* all = (const float*)d_in[0];
    const float* h0  = (const float*)d_in[1];
    const float* Wr  = (const float*)d_in[2];
    const float* Ur  = (const float*)d_in[3];
    const float* Cr  = (const float*)d_in[4];
    const float* Wz  = (const float*)d_in[5];
    const float* Uz  = (const float*)d_in[6];
    const float* Cz  = (const float*)d_in[7];
    const float* Wc  = (const float*)d_in[8];
    const float* Uc  = (const float*)d_in[9];
    const float* Cc  = (const float*)d_in[10];
    float* out = (float*)d_out;

    static int smem_set = 0;
    if (!smem_set) {
        cudaFuncSetAttribute(recurrent, cudaFuncAttributeMaxDynamicSharedMemorySize, REC_SMEM);
        smem_set = 1;
    }

    pack_a_split<<<4096, 256>>>(all);
    pack_w_split<<<2048, 256>>>(Wr, Cr, Wz, Cz, Wc, Cc);
    pack_UrzF<<<2048, 256>>>(Ur, Uz);
    pack_UcF<<<1024, 256>>>(Uc);
    pack_h_split<<<256, 256>>>(h0);
    gemm_pre_mma<<<dim3(24, 128), 256>>>();
    recurrent<<<NBLK, 256, REC_SMEM>>>(out);
}

// round 8
// speedup vs baseline: 1.8391x; 1.2245x over previous
#include <cuda_runtime.h>
#include <cuda_bf16.h>
#include <cuda_fp16.h>
#include <math.h>
#include <stdint.h>

#define NB 64
#define NTT 256
#define NU 1024
#define KX 2048
#define N3 3072
#define NBLK 128
#define SROW 136            // halves per staged row (128 + 8 pad)
#define SBUFH (64 * SROW)   // halves per staged tile

// ------------------------- device scratch (no allocs allowed) ----------------
__device__ __align__(16) __nv_bfloat16 g_Ahi[(size_t)16384 * KX];
__device__ __align__(16) __nv_bfloat16 g_Alo[(size_t)16384 * KX];
__device__ __align__(16) __nv_bfloat16 g_Wth[(size_t)N3 * KX];
__device__ __align__(16) __nv_bfloat16 g_Wtl[(size_t)N3 * KX];
__device__ __align__(16) float g_G[(size_t)NTT * NB * N3];
__device__ __align__(16) uint4 g_UrzF[256 * 64 * 32];   // frag-packed [U_r|U_z] f16 hi/lo
__device__ __align__(16) uint4 g_UcF[128 * 64 * 32];    // frag-packed U f16 hi/lo
__device__ __align__(16) float g_h[NB * NU];
__device__ __align__(16) __half g_hf[NB * NU];
__device__ __align__(16) float g_z[NB * NU];
__device__ __align__(16) __half g_a2f[NB * NU];

// grid barrier state (monotonic generation -> safe across graph replays)
__device__ unsigned g_cnt = 0;
__device__ unsigned g_gen = 0;

__device__ __forceinline__ void grid_bar() {
    __syncthreads();
    if (threadIdx.x == 0) {
        unsigned gen = *((volatile unsigned*)&g_gen);
        __threadfence();
        if (atomicAdd(&g_cnt, 1u) == NBLK - 1u) {
            g_cnt = 0;
            __threadfence();
            atomicAdd(&g_gen, 1u);
        } else {
            unsigned spins = 0;
            while (*((volatile unsigned*)&g_gen) == gen) {
                if (++spins > 4096u) __nanosleep(40);
                if (spins > 4000000u) break;   // safety valve: never hang
            }
        }
        __threadfence();
    }
    __syncthreads();
}

// ------------------------- mma.sync helpers (sm_80+ ISA) ---------------------
static __device__ __forceinline__ uint32_t smem_u32(const void* p) {
    uint32_t a;
    asm("{ .reg .u64 t; cvta.to.shared.u64 t, %1; cvt.u32.u64 %0, t; }" : "=r"(a) : "l"(p));
    return a;
}
#define LDSM_X4(r0, r1, r2, r3, a) \
    asm volatile("ldmatrix.sync.aligned.m8n8.x4.shared.b16 {%0,%1,%2,%3}, [%4];" \
                 : "=r"(r0), "=r"(r1), "=r"(r2), "=r"(r3) : "r"(a))
#define MMA_BF16(d, a0, a1, a2, a3, b0, b1) \
    asm volatile("mma.sync.aligned.m16n8k16.row.col.f32.bf16.bf16.f32 " \
                 "{%0,%1,%2,%3}, {%4,%5,%6,%7}, {%8,%9}, {%0,%1,%2,%3};" \
                 : "+f"((d)[0]), "+f"((d)[1]), "+f"((d)[2]), "+f"((d)[3]) \
                 : "r"(a0), "r"(a1), "r"(a2), "r"(a3), "r"(b0), "r"(b1))
#define MMA_F16(d, a0, a1, a2, a3, b0, b1) \
    asm volatile("mma.sync.aligned.m16n8k16.row.col.f32.f16.f16.f32 " \
                 "{%0,%1,%2,%3}, {%4,%5,%6,%7}, {%8,%9}, {%0,%1,%2,%3};" \
                 : "+f"((d)[0]), "+f"((d)[1]), "+f"((d)[2]), "+f"((d)[3]) \
                 : "r"(a0), "r"(a1), "r"(a2), "r"(a3), "r"(b0), "r"(b1))

static __device__ __forceinline__ uint32_t pack2hi(float x, float y) {
    __nv_bfloat162 v = {__float2bfloat16(x), __float2bfloat16(y)};
    return *(uint32_t*)&v;
}
static __device__ __forceinline__ uint32_t pack2lo(float x, float y) {
    float hx = __bfloat162float(__float2bfloat16(x));
    float hy = __bfloat162float(__float2bfloat16(y));
    __nv_bfloat162 v = {__float2bfloat16(x - hx), __float2bfloat16(y - hy)};
    return *(uint32_t*)&v;
}
static __device__ __forceinline__ uint32_t pack2hf(float x, float y) {
    __half2 v = {__float2half(x), __float2half(y)};
    return *(uint32_t*)&v;
}
static __device__ __forceinline__ uint32_t pack2lf(float x, float y) {
    float hx = __half2float(__float2half(x));
    float hy = __half2float(__float2half(y));
    __half2 v = {__float2half(x - hx), __float2half(y - hy)};
    return *(uint32_t*)&v;
}
static __device__ __forceinline__ float hsig(float x) {
    return fminf(fmaxf(0.2f * x + 0.5f, 0.0f), 1.0f);
}

// ------------------------- packing / init -----------------------------------
__global__ void pack_a_split(const float* __restrict__ all) {
    size_t n = (size_t)16384 * KX;
    size_t stride = (size_t)gridDim.x * blockDim.x;
    for (size_t i = blockIdx.x * (size_t)blockDim.x + threadIdx.x; i < n; i += stride) {
        float v = all[i];
        __nv_bfloat16 hi = __float2bfloat16(v);
        g_Ahi[i] = hi;
        g_Alo[i] = __float2bfloat16(v - __bfloat162float(hi));
    }
}

__global__ void pack_w_split(const float* __restrict__ Wr, const float* __restrict__ Cr,
                             const float* __restrict__ Wz, const float* __restrict__ Cz,
                             const float* __restrict__ Wc, const float* __restrict__ Cc) {
    size_t n = (size_t)N3 * KX;
    size_t stride = (size_t)gridDim.x * blockDim.x;
    for (size_t i = blockIdx.x * (size_t)blockDim.x + threadIdx.x; i < n; i += stride) {
        int nn = (int)(i >> 11);
        int k  = (int)(i & 2047);
        int sel = nn >> 10, j = nn & 1023;
        float v;
        if (k < 1024) {
            const float* s = (sel == 0) ? Cr : (sel == 1) ? Cz : Cc;
            v = s[k * NU + j];
        } else {
            const float* s = (sel == 0) ? Wr : (sel == 1) ? Wz : Wc;
            v = s[(k - 1024) * NU + j];
        }
        __nv_bfloat16 hi = __float2bfloat16(v);
        g_Wth[i] = hi;
        g_Wtl[i] = __float2bfloat16(v - __bfloat162float(hi));
    }
}

// frag-major f16 hi/lo packing of [U_r | U_z]
__global__ void pack_UrzF(const float* __restrict__ Ur, const float* __restrict__ Uz) {
    int fid = blockIdx.x * blockDim.x + threadIdx.x;   // 524288
    int nt = fid >> 11, kc = (fid >> 5) & 63, lane = fid & 31;
    int n = nt * 8 + (lane >> 2);
    int k0 = kc * 16 + (lane & 3) * 2;
    const float* src = (n < 1024) ? Ur : Uz;
    int nn = n & 1023;
    float v00 = src[(k0 + 0) * NU + nn], v01 = src[(k0 + 1) * NU + nn];
    float v10 = src[(k0 + 8) * NU + nn], v11 = src[(k0 + 9) * NU + nn];
    g_UrzF[fid] = make_uint4(pack2hf(v00, v01), pack2hf(v10, v11),
                             pack2lf(v00, v01), pack2lf(v10, v11));
}

__global__ void pack_UcF(const float* __restrict__ Uc) {
    int fid = blockIdx.x * blockDim.x + threadIdx.x;   // 262144
    int nt = fid >> 11, kc = (fid >> 5) & 63, lane = fid & 31;
    int n = nt * 8 + (lane >> 2);
    int k0 = kc * 16 + (lane & 3) * 2;
    float v00 = Uc[(k0 + 0) * NU + n], v01 = Uc[(k0 + 1) * NU + n];
    float v10 = Uc[(k0 + 8) * NU + n], v11 = Uc[(k0 + 9) * NU + n];
    g_UcF[fid] = make_uint4(pack2hf(v00, v01), pack2hf(v10, v11),
                            pack2lf(v00, v01), pack2lf(v10, v11));
}

__global__ void pack_h_split(const float* __restrict__ h0) {
    int i = blockIdx.x * blockDim.x + threadIdx.x;     // 65536
    float v = h0[i];
    g_h[i] = v;
    g_hf[i] = __float2half(v);
}

// ------------------------- mma.sync precompute GEMM (unchanged, passing) -----
#define SPAD 40

__global__ __launch_bounds__(256) void gemm_pre_mma() {
    __shared__ __align__(16) __nv_bfloat16 sAh[128 * SPAD];
    __shared__ __align__(16) __nv_bfloat16 sAl[128 * SPAD];
    __shared__ __align__(16) __nv_bfloat16 sBh[128 * SPAD];
    __shared__ __align__(16) __nv_bfloat16 sBl[128 * SPAD];

    const int tid = threadIdx.x;
    const int wid = tid >> 5, lane = tid & 31;
    const int wm = wid >> 2, wn = wid & 3;
    const int bn = blockIdx.x, bm = blockIdx.y;

    float acc[4][4][4];
#pragma unroll
    for (int i = 0; i < 4; i++)
#pragma unroll
        for (int j = 0; j < 4; j++)
#pragma unroll
            for (int k = 0; k < 4; k++) acc[i][j][k] = 0.0f;

    const uint32_t aHiB = smem_u32(sAh), aLoB = smem_u32(sAl);
    const uint32_t bHiB = smem_u32(sBh), bLoB = smem_u32(sBl);

    const int aRowL = wm * 64 + (lane & 15);
    const int aColL = (lane >> 4) * 8;
    const int bRowL = wn * 32 + (lane & 7) + ((lane >> 4) ? 8 : 0);
    const int bColL = ((lane >> 3) & 1) * 8;

    const int s0 = tid, s1 = tid + 256;
    const int r0 = s0 >> 2, c0 = (s0 & 3) << 3;
    const int r1 = s1 >> 2, c1 = (s1 & 3) << 3;

    for (int kb = 0; kb < KX; kb += 32) {
        __syncthreads();
        {
            size_t ga0 = (size_t)(bm * 128 + r0) * KX + kb + c0;
            size_t ga1 = (size_t)(bm * 128 + r1) * KX + kb + c1;
            *(float4*)&sAh[r0 * SPAD + c0] = *(const float4*)&g_Ahi[ga0];
            *(float4*)&sAh[r1 * SPAD + c1] = *(const float4*)&g_Ahi[ga1];
            *(float4*)&sAl[r0 * SPAD + c0] = *(const float4*)&g_Alo[ga0];
            *(float4*)&sAl[r1 * SPAD + c1] = *(const float4*)&g_Alo[ga1];
            size_t gb0 = (size_t)(bn * 128 + r0) * KX + kb + c0;
            size_t gb1 = (size_t)(bn * 128 + r1) * KX + kb + c1;
            *(float4*)&sBh[r0 * SPAD + c0] = *(const float4*)&g_Wth[gb0];
            *(float4*)&sBh[r1 * SPAD + c1] = *(const float4*)&g_Wth[gb1];
            *(float4*)&sBl[r0 * SPAD + c0] = *(const float4*)&g_Wtl[gb0];
            *(float4*)&sBl[r1 * SPAD + c1] = *(const float4*)&g_Wtl[gb1];
        }
        __syncthreads();

#pragma unroll
        for (int ks = 0; ks < 2; ks++) {
            const int kc = ks * 16;
            uint32_t ah[4][4], al[4][4], bh[4][2], bl[4][2];
#pragma unroll
            for (int mi = 0; mi < 4; mi++) {
                uint32_t ad = aHiB + (uint32_t)(((aRowL + mi * 16) * SPAD + aColL + kc) * 2);
                LDSM_X4(ah[mi][0], ah[mi][1], ah[mi][2], ah[mi][3], ad);
            }
#pragma unroll
            for (int np = 0; np < 2; np++) {
                uint32_t bd = bHiB + (uint32_t)(((bRowL + np * 16) * SPAD + bColL + kc) * 2);
                LDSM_X4(bh[np * 2][0], bh[np * 2][1], bh[np * 2 + 1][0], bh[np * 2 + 1][1], bd);
            }
#pragma unroll
            for (int mi = 0; mi < 4; mi++)
#pragma unroll
                for (int ni = 0; ni < 4; ni++)
                    MMA_BF16(acc[mi][ni], ah[mi][0], ah[mi][1], ah[mi][2], ah[mi][3],
                             bh[ni][0], bh[ni][1]);
#pragma unroll
            for (int np = 0; np < 2; np++) {
                uint32_t bd = bLoB + (uint32_t)(((bRowL + np * 16) * SPAD + bColL + kc) * 2);
                LDSM_X4(bl[np * 2][0], bl[np * 2][1], bl[np * 2 + 1][0], bl[np * 2 + 1][1], bd);
            }
#pragma unroll
            for (int mi = 0; mi < 4; mi++)
#pragma unroll
                for (int ni = 0; ni < 4; ni++)
                    MMA_BF16(acc[mi][ni], ah[mi][0], ah[mi][1], ah[mi][2], ah[mi][3],
                             bl[ni][0], bl[ni][1]);
#pragma unroll
            for (int mi = 0; mi < 4; mi++) {
                uint32_t ad = aLoB + (uint32_t)(((aRowL + mi * 16) * SPAD + aColL + kc) * 2);
                LDSM_X4(al[mi][0], al[mi][1], al[mi][2], al[mi][3], ad);
            }
#pragma unroll
            for (int mi = 0; mi < 4; mi++)
#pragma unroll
                for (int ni = 0; ni < 4; ni++)
                    MMA_BF16(acc[mi][ni], al[mi][0], al[mi][1], al[mi][2], al[mi][3],
                             bh[ni][0], bh[ni][1]);
        }
    }

#pragma unroll
    for (int mi = 0; mi < 4; mi++) {
        int mA = bm * 128 + wm * 64 + mi * 16 + (lane >> 2);
        int mB = mA + 8;
        int bA = mA >> 8, tA = mA & 255;
        int bB = mB >> 8, tB = mB & 255;
        float* oA = g_G + (size_t)(tA * NB + bA) * N3;
        float* oB = g_G + (size_t)(tB * NB + bB) * N3;
        int colb = bn * 128 + wn * 32 + (lane & 3) * 2;
#pragma unroll
        for (int ni = 0; ni < 4; ni++) {
            int c = colb + ni * 8;
            *(float2*)(oA + c) = make_float2(acc[mi][ni][0], acc[mi][ni][1]);
            *(float2*)(oB + c) = make_float2(acc[mi][ni][2], acc[mi][ni][3]);
        }
    }
}

// ------------------------- persistent recurrent kernel (f16 tensorized) ------
// 128 CTAs x 256 threads. Phase A: CTA owns 16 gate cols; fused act_rz.
// Phase B: CTA owns 8 output cols (K split 2x in-CTA); fused act_h.
static __device__ __forceinline__ void stage_f16(__half* smh, const __half* gh,
                                                 int kb, int tid) {
#pragma unroll
    for (int it = 0; it < 4; it++) {
        int slot = it * 256 + tid;
        int row = slot >> 4, grp = slot & 15;
        *(uint4*)(smh + row * SROW + grp * 8) = *(const uint4*)(gh + row * NU + kb + grp * 8);
    }
}

__global__ __launch_bounds__(256, 1) void recurrent(float* __restrict__ out) {
    extern __shared__ __align__(16) char smraw[];
    __half* sm = (__half*)smraw;                       // 2 x SBUFH halves
    float* red = (float*)(smraw + 2 * SBUFH * 2);
    const int bx = blockIdx.x;
    const int tid = threadIdx.x;
    const int wid = tid >> 5, lane = tid & 31;
    const int wm = wid >> 1, ws = wid & 1;             // phase A: ws=n8 tile; phase B: ws=k half

    const int lrow = lane & 15, lcol = (lane >> 4) * 8;
    const int erow = wm * 16 + (lane >> 2);
    const int ecol2 = (lane & 3) * 2;

    for (int t = 0; t < NTT; t++) {
        // ============ phase A: h @ [U_r|U_z], cols bx*16..+16, fused act_rz =====
        {
            float acc[4] = {0.f, 0.f, 0.f, 0.f};
            const uint4* bfr = g_UrzF + ((size_t)(bx * 2 + ws) * 64) * 32 + lane;
            stage_f16(sm, g_hf, 0, tid);
            __syncthreads();
            for (int i = 0; i < 8; i++) {
                if (i < 7) stage_f16(sm + ((i + 1) & 1) * SBUFH, g_hf, (i + 1) * 128, tid);
                uint32_t baseH = smem_u32(sm + (i & 1) * SBUFH + (wm * 16 + lrow) * SROW + lcol);
#pragma unroll
                for (int kc = 0; kc < 8; kc++) {
                    uint32_t a0, a1, a2, a3;
                    LDSM_X4(a0, a1, a2, a3, baseH + kc * 32);
                    uint4 bv = bfr[(i * 8 + kc) * 32];
                    MMA_F16(acc, a0, a1, a2, a3, bv.x, bv.y);
                    MMA_F16(acc, a0, a1, a2, a3, bv.z, bv.w);
                }
                __syncthreads();
            }
            // fused epilogue
            const int colg = bx * 16 + ws * 8 + ecol2;
            float s00 = acc[0] + g_G[((size_t)t * NB + erow) * N3 + colg];
            float s01 = acc[1] + g_G[((size_t)t * NB + erow) * N3 + colg + 1];
            float s10 = acc[2] + g_G[((size_t)t * NB + erow + 8) * N3 + colg];
            float s11 = acc[3] + g_G[((size_t)t * NB + erow + 8) * N3 + colg + 1];
            if (bx < 64) {                                  // r gate -> a2 = h*r (f16)
                float2 h0 = *(const float2*)&g_h[erow * NU + colg];
                float2 h1 = *(const float2*)&g_h[(erow + 8) * NU + colg];
                __half2 a01 = {__float2half(h0.x * hsig(s00)), __float2half(h0.y * hsig(s01))};
                __half2 a23 = {__float2half(h1.x * hsig(s10)), __float2half(h1.y * hsig(s11))};
                *(__half2*)&g_a2f[erow * NU + colg] = a01;
                *(__half2*)&g_a2f[(erow + 8) * NU + colg] = a23;
            } else {                                        // z gate
                int j = colg - 1024;
                *(float2*)&g_z[erow * NU + j] = make_float2(hsig(s00), hsig(s01));
                *(float2*)&g_z[(erow + 8) * NU + j] = make_float2(hsig(s10), hsig(s11));
            }
        }
        grid_bar();
        // ============ phase B: (h*r) @ U, cols bx*8..+8, fused act_h ============
        {
            float acc[4] = {0.f, 0.f, 0.f, 0.f};
            const uint4* bfr = g_UcF + ((size_t)bx * 64) * 32 + lane;
            for (int r = 0; r < 4; r++) {
                __syncthreads();
                stage_f16(sm, g_a2f, r * 128, tid);
                stage_f16(sm + SBUFH, g_a2f, 512 + r * 128, tid);
                __syncthreads();
                uint32_t baseH = smem_u32(sm + ws * SBUFH + (wm * 16 + lrow) * SROW + lcol);
#pragma unroll
                for (int kc = 0; kc < 8; kc++) {
                    uint32_t a0, a1, a2, a3;
                    LDSM_X4(a0, a1, a2, a3, baseH + kc * 32);
                    uint4 bv = bfr[(ws * 32 + r * 8 + kc) * 32];
                    MMA_F16(acc, a0, a1, a2, a3, bv.x, bv.y);
                    MMA_F16(acc, a0, a1, a2, a3, bv.z, bv.w);
                }
            }
            *(float2*)&red[((ws * 64) + erow) * 8 + ecol2] = make_float2(acc[0], acc[1]);
            *(float2*)&red[((ws * 64) + erow + 8) * 8 + ecol2] = make_float2(acc[2], acc[3]);
            __syncthreads();
#pragma unroll
            for (int o = tid; o < 512; o += 256) {
                int b = o >> 3, jj = o & 7;
                int j = bx * 8 + jj;
                float s = red[b * 8 + jj] + red[(64 + b) * 8 + jj]
                        + g_G[((size_t)t * NB + b) * N3 + 2048 + j];
                float hc = tanhf(s);
                float z = g_z[b * NU + j], h = g_h[b * NU + j];
                float hn = (1.0f - z) * h + z * hc;
                g_h[b * NU + j] = hn;
                g_hf[b * NU + j] = __float2half(hn);
                out[((size_t)b * NTT + t) * NU + j] = hn;
            }
        }
        grid_bar();
    }
}

// ------------------------- launch -------------------------------------------
#define REC_SMEM (2 * SBUFH * 2 + 4096)

extern "C" void kernel_launch(void* const* d_in, const int* in_sizes, int n_in,
                              void* d_out, int out_size) {
    const float* all = (const float*)d_in[0];
    const float* h0  = (const float*)d_in[1];
    const float* Wr  = (const float*)d_in[2];
    const float* Ur  = (const float*)d_in[3];
    const float* Cr  = (const float*)d_in[4];
    const float* Wz  = (const float*)d_in[5];
    const float* Uz  = (const float*)d_in[6];
    const float* Cz  = (const float*)d_in[7];
    const float* Wc  = (const float*)d_in[8];
    const float* Uc  = (const float*)d_in[9];
    const float* Cc  = (const float*)d_in[10];
    float* out = (float*)d_out;

    static int smem_set = 0;
    if (!smem_set) {
        cudaFuncSetAttribute(recurrent, cudaFuncAttributeMaxDynamicSharedMemorySize, REC_SMEM);
        smem_set = 1;
    }

    pack_a_split<<<4096, 256>>>(all);
    pack_w_split<<<2048, 256>>>(Wr, Cr, Wz, Cz, Wc, Cc);
    pack_UrzF<<<2048, 256>>>(Ur, Uz);
    pack_UcF<<<1024, 256>>>(Uc);
    pack_h_split<<<256, 256>>>(h0);
    gemm_pre_mma<<<dim3(24, 128), 256>>>();
    recurrent<<<NBLK, 256, REC_SMEM>>>(out);
}

// round 9
// speedup vs baseline: 2.0771x; 1.1294x over previous
#include <cuda_runtime.h>
#include <cuda_bf16.h>
#include <cuda_fp16.h>
#include <math.h>
#include <stdint.h>

#define NB 64
#define NTT 256
#define NU 1024
#define KX 2048
#define N3 3072
#define NBLK 128
#define SROW2 1032          // halves per fully-staged row (1024 + 8 pad)

// ------------------------- device scratch (no allocs allowed) ----------------
__device__ __align__(16) uint4 g_AFh[(size_t)1024 * 128 * 32];  // A frag-major bf16 hi (64MB)
__device__ __align__(16) uint4 g_AFl[(size_t)1024 * 128 * 32];  // A frag-major bf16 lo (64MB)
__device__ __align__(16) uint4 g_WF[(size_t)384 * 128 * 32];    // W frag-major {b0h,b1h,b0l,b1l} (24MB)
__device__ __align__(16) float g_G[(size_t)NTT * NB * N3];
__device__ __align__(16) uint4 g_UrzF[256 * 64 * 32];           // frag-packed [U_r|U_z] f16 hi/lo
__device__ __align__(16) uint4 g_UcF[128 * 64 * 32];            // frag-packed U f16 hi/lo
__device__ __align__(16) float g_h[NB * NU];
__device__ __align__(16) __half g_hf[NB * NU];
__device__ __align__(16) float g_z[NB * NU];
__device__ __align__(16) __half g_a2f[NB * NU];

// grid barrier state (monotonic generation -> safe across graph replays)
__device__ unsigned g_cnt = 0;
__device__ unsigned g_gen = 0;

__device__ __forceinline__ void grid_bar() {
    __syncthreads();
    if (threadIdx.x == 0) {
        unsigned gen = *((volatile unsigned*)&g_gen);
        __threadfence();
        if (atomicAdd(&g_cnt, 1u) == NBLK - 1u) {
            g_cnt = 0;
            __threadfence();
            atomicAdd(&g_gen, 1u);
        } else {
            unsigned spins = 0;
            while (*((volatile unsigned*)&g_gen) == gen) {
                if (++spins > 4096u) __nanosleep(40);
                if (spins > 4000000u) break;   // safety valve: never hang
            }
        }
        __threadfence();
    }
    __syncthreads();
}

// ------------------------- mma.sync helpers (sm_80+ ISA) ---------------------
static __device__ __forceinline__ uint32_t smem_u32(const void* p) {
    uint32_t a;
    asm("{ .reg .u64 t; cvta.to.shared.u64 t, %1; cvt.u32.u64 %0, t; }" : "=r"(a) : "l"(p));
    return a;
}
#define LDSM_X4(r0, r1, r2, r3, a) \
    asm volatile("ldmatrix.sync.aligned.m8n8.x4.shared.b16 {%0,%1,%2,%3}, [%4];" \
                 : "=r"(r0), "=r"(r1), "=r"(r2), "=r"(r3) : "r"(a))
#define MMA_BF16(d, a0, a1, a2, a3, b0, b1) \
    asm volatile("mma.sync.aligned.m16n8k16.row.col.f32.bf16.bf16.f32 " \
                 "{%0,%1,%2,%3}, {%4,%5,%6,%7}, {%8,%9}, {%0,%1,%2,%3};" \
                 : "+f"((d)[0]), "+f"((d)[1]), "+f"((d)[2]), "+f"((d)[3]) \
                 : "r"(a0), "r"(a1), "r"(a2), "r"(a3), "r"(b0), "r"(b1))
#define MMA_F16(d, a0, a1, a2, a3, b0, b1) \
    asm volatile("mma.sync.aligned.m16n8k16.row.col.f32.f16.f16.f32 " \
                 "{%0,%1,%2,%3}, {%4,%5,%6,%7}, {%8,%9}, {%0,%1,%2,%3};" \
                 : "+f"((d)[0]), "+f"((d)[1]), "+f"((d)[2]), "+f"((d)[3]) \
                 : "r"(a0), "r"(a1), "r"(a2), "r"(a3), "r"(b0), "r"(b1))

static __device__ __forceinline__ uint32_t pack2hi(float x, float y) {
    __nv_bfloat162 v = {__float2bfloat16(x), __float2bfloat16(y)};
    return *(uint32_t*)&v;
}
static __device__ __forceinline__ uint32_t pack2lo(float x, float y) {
    float hx = __bfloat162float(__float2bfloat16(x));
    float hy = __bfloat162float(__float2bfloat16(y));
    __nv_bfloat162 v = {__float2bfloat16(x - hx), __float2bfloat16(y - hy)};
    return *(uint32_t*)&v;
}
static __device__ __forceinline__ uint32_t pack2hf(float x, float y) {
    __half2 v = {__float2half(x), __float2half(y)};
    return *(uint32_t*)&v;
}
static __device__ __forceinline__ uint32_t pack2lf(float x, float y) {
    float hx = __half2float(__float2half(x));
    float hy = __half2float(__float2half(y));
    __half2 v = {__float2half(x - hx), __float2half(y - hy)};
    return *(uint32_t*)&v;
}
static __device__ __forceinline__ float hsig(float x) {
    return fminf(fmaxf(0.2f * x + 0.5f, 0.0f), 1.0f);
}

// ------------------------- packing / init -----------------------------------
// A fragment layout (m16n8k16 .row A): lane l -> row=(l>>2), col=(l&3)*2;
// a0=(r,c..c+1) a1=(r+8,c..) a2=(r,c+8..) a3=(r+8,c+8..)
__global__ void pack_AF(const float* __restrict__ all) {
    int fid = blockIdx.x * blockDim.x + threadIdx.x;   // 4194304
    int lane = fid & 31, kc = (fid >> 5) & 127, m16t = fid >> 12;
    int row = m16t * 16 + (lane >> 2);
    int col = kc * 16 + (lane & 3) * 2;
    const float* p = all + (size_t)row * KX + col;
    float a00 = p[0], a01 = p[1];
    float a10 = p[8 * KX], a11 = p[8 * KX + 1];
    float a20 = p[8], a21 = p[9];
    float a30 = p[8 * KX + 8], a31 = p[8 * KX + 9];
    g_AFh[fid] = make_uint4(pack2hi(a00, a01), pack2hi(a10, a11),
                            pack2hi(a20, a21), pack2hi(a30, a31));
    g_AFl[fid] = make_uint4(pack2lo(a00, a01), pack2lo(a10, a11),
                            pack2lo(a20, a21), pack2lo(a30, a31));
}

// W fragment layout (.col B): lane l -> col n=(l>>2), k=(l&3)*2; b0=(k..k+1,n) b1=(k+8..k+9,n)
__global__ void pack_WF(const float* __restrict__ Wr, const float* __restrict__ Cr,
                        const float* __restrict__ Wz, const float* __restrict__ Cz,
                        const float* __restrict__ Wc, const float* __restrict__ Cc) {
    int fid = blockIdx.x * blockDim.x + threadIdx.x;   // 1572864
    int lane = fid & 31, kc = (fid >> 5) & 127, n8t = fid >> 12;
    int n = n8t * 8 + (lane >> 2);
    int k0 = kc * 16 + (lane & 3) * 2;
    int sel = n >> 10, j = n & 1023;
    const float* C = (sel == 0) ? Cr : (sel == 1) ? Cz : Cc;
    const float* W = (sel == 0) ? Wr : (sel == 1) ? Wz : Wc;
    auto wat = [&](int k) -> float {
        return (k < 1024) ? C[k * NU + j] : W[(k - 1024) * NU + j];
    };
    float b00 = wat(k0), b01 = wat(k0 + 1);
    float b10 = wat(k0 + 8), b11 = wat(k0 + 9);
    g_WF[fid] = make_uint4(pack2hi(b00, b01), pack2hi(b10, b11),
                           pack2lo(b00, b01), pack2lo(b10, b11));
}

__global__ void pack_UrzF(const float* __restrict__ Ur, const float* __restrict__ Uz) {
    int fid = blockIdx.x * blockDim.x + threadIdx.x;   // 524288
    int nt = fid >> 11, kc = (fid >> 5) & 63, lane = fid & 31;
    int n = nt * 8 + (lane >> 2);
    int k0 = kc * 16 + (lane & 3) * 2;
    const float* src = (n < 1024) ? Ur : Uz;
    int nn = n & 1023;
    float v00 = src[(k0 + 0) * NU + nn], v01 = src[(k0 + 1) * NU + nn];
    float v10 = src[(k0 + 8) * NU + nn], v11 = src[(k0 + 9) * NU + nn];
    g_UrzF[fid] = make_uint4(pack2hf(v00, v01), pack2hf(v10, v11),
                             pack2lf(v00, v01), pack2lf(v10, v11));
}

__global__ void pack_UcF(const float* __restrict__ Uc) {
    int fid = blockIdx.x * blockDim.x + threadIdx.x;   // 262144
    int nt = fid >> 11, kc = (fid >> 5) & 63, lane = fid & 31;
    int n = nt * 8 + (lane >> 2);
    int k0 = kc * 16 + (lane & 3) * 2;
    float v00 = Uc[(k0 + 0) * NU + n], v01 = Uc[(k0 + 1) * NU + n];
    float v10 = Uc[(k0 + 8) * NU + n], v11 = Uc[(k0 + 9) * NU + n];
    g_UcF[fid] = make_uint4(pack2hf(v00, v01), pack2hf(v10, v11),
                            pack2lf(v00, v01), pack2lf(v10, v11));
}

__global__ void pack_h_split(const float* __restrict__ h0) {
    int i = blockIdx.x * blockDim.x + threadIdx.x;     // 65536
    float v = h0[i];
    g_h[i] = v;
    g_hf[i] = __float2half(v);
}

// ------------------------- frag-direct precompute GEMM -----------------------
// C[16384,3072] = A@W, bf16 3-term split, all operands LDG'd as fragments.
// grid (24 bn, 128 bm), 8 warps: wm (2) x wn (4); warp tile 64x32.
__global__ __launch_bounds__(256) void gemm_pre_f() {
    const int tid = threadIdx.x;
    const int wid = tid >> 5, lane = tid & 31;
    const int wm = wid >> 2, wn = wid & 3;
    const int bn = blockIdx.x, bm = blockIdx.y;

    float acc[4][4][4];
#pragma unroll
    for (int i = 0; i < 4; i++)
#pragma unroll
        for (int j = 0; j < 4; j++)
#pragma unroll
            for (int k = 0; k < 4; k++) acc[i][j][k] = 0.0f;

    const uint4* ah = g_AFh + ((size_t)(bm * 8 + wm * 4) * 128) * 32 + lane;
    const uint4* al = g_AFl + ((size_t)(bm * 8 + wm * 4) * 128) * 32 + lane;
    const uint4* bp = g_WF  + ((size_t)(bn * 16 + wn * 4) * 128) * 32 + lane;

    for (int kc = 0; kc < 128; kc++) {
        uint4 af[4], alf[4], bf[4];
#pragma unroll
        for (int mi = 0; mi < 4; mi++) {
            af[mi]  = ah[(size_t)(mi * 128 + kc) * 32];
            alf[mi] = al[(size_t)(mi * 128 + kc) * 32];
        }
#pragma unroll
        for (int ni = 0; ni < 4; ni++) bf[ni] = bp[(size_t)(ni * 128 + kc) * 32];
#pragma unroll
        for (int mi = 0; mi < 4; mi++)
#pragma unroll
            for (int ni = 0; ni < 4; ni++)
                MMA_BF16(acc[mi][ni], af[mi].x, af[mi].y, af[mi].z, af[mi].w,
                         bf[ni].x, bf[ni].y);
#pragma unroll
        for (int mi = 0; mi < 4; mi++)
#pragma unroll
            for (int ni = 0; ni < 4; ni++)
                MMA_BF16(acc[mi][ni], af[mi].x, af[mi].y, af[mi].z, af[mi].w,
                         bf[ni].z, bf[ni].w);
#pragma unroll
        for (int mi = 0; mi < 4; mi++)
#pragma unroll
            for (int ni = 0; ni < 4; ni++)
                MMA_BF16(acc[mi][ni], alf[mi].x, alf[mi].y, alf[mi].z, alf[mi].w,
                         bf[ni].x, bf[ni].y);
    }

#pragma unroll
    for (int mi = 0; mi < 4; mi++) {
        int mA = bm * 128 + wm * 64 + mi * 16 + (lane >> 2);
        int mB = mA + 8;
        int bA = mA >> 8, tA = mA & 255;
        int bB = mB >> 8, tB = mB & 255;
        float* oA = g_G + (size_t)(tA * NB + bA) * N3;
        float* oB = g_G + (size_t)(tB * NB + bB) * N3;
        int colb = bn * 128 + wn * 32 + (lane & 3) * 2;
#pragma unroll
        for (int ni = 0; ni < 4; ni++) {
            int c = colb + ni * 8;
            *(float2*)(oA + c) = make_float2(acc[mi][ni][0], acc[mi][ni][1]);
            *(float2*)(oB + c) = make_float2(acc[mi][ni][2], acc[mi][ni][3]);
        }
    }
}

// ------------------------- persistent recurrent kernel (full-stage) ----------
// 128 CTAs x 256 thr. h/a2 staged ENTIRELY in smem (132KB) once per phase;
// MMA loops run sync-free. Phase A fused act_rz; phase B fused act_h.
__global__ __launch_bounds__(256, 1) void recurrent(float* __restrict__ out) {
    extern __shared__ __align__(16) char smraw[];
    __half* sm = (__half*)smraw;                        // 64 x SROW2 halves
    float* red = (float*)(smraw + 64 * SROW2 * 2);
    const int bx = blockIdx.x;
    const int tid = threadIdx.x;
    const int wid = tid >> 5, lane = tid & 31;
    const int wm = wid >> 1, ws = wid & 1;

    const int lrow = lane & 15, lcol = (lane >> 4) * 8;
    const int erow = wm * 16 + (lane >> 2);
    const int ecol2 = (lane & 3) * 2;
    const uint32_t aBase = smem_u32(sm) + (uint32_t)(((wm * 16 + lrow) * SROW2 + lcol) * 2);

    for (int t = 0; t < NTT; t++) {
        // ---- stage full h (64x1024 f16) ----
#pragma unroll
        for (int it = 0; it < 32; it++) {
            int slot = it * 256 + tid;
            int row = slot >> 7, grp = slot & 127;
            *(uint4*)(sm + row * SROW2 + grp * 8) = *(const uint4*)(g_hf + row * NU + grp * 8);
        }
        __syncthreads();
        // ---- phase A: h @ [U_r|U_z], cols bx*16..+16, fused act_rz ----
        {
            float acc[4] = {0.f, 0.f, 0.f, 0.f};
            const uint4* bfr = g_UrzF + ((size_t)(bx * 2 + ws) * 64) * 32 + lane;
#pragma unroll 8
            for (int kc = 0; kc < 64; kc++) {
                uint32_t a0, a1, a2, a3;
                LDSM_X4(a0, a1, a2, a3, aBase + kc * 32);
                uint4 bv = bfr[(size_t)kc * 32];
                MMA_F16(acc, a0, a1, a2, a3, bv.x, bv.y);
                MMA_F16(acc, a0, a1, a2, a3, bv.z, bv.w);
            }
            const int colg = bx * 16 + ws * 8 + ecol2;
            float s00 = acc[0] + g_G[((size_t)t * NB + erow) * N3 + colg];
            float s01 = acc[1] + g_G[((size_t)t * NB + erow) * N3 + colg + 1];
            float s10 = acc[2] + g_G[((size_t)t * NB + erow + 8) * N3 + colg];
            float s11 = acc[3] + g_G[((size_t)t * NB + erow + 8) * N3 + colg + 1];
            if (bx < 64) {                                  // r gate -> a2 = h*r
                float2 h0 = *(const float2*)&g_h[erow * NU + colg];
                float2 h1 = *(const float2*)&g_h[(erow + 8) * NU + colg];
                __half2 a01 = {__float2half(h0.x * hsig(s00)), __float2half(h0.y * hsig(s01))};
                __half2 a23 = {__float2half(h1.x * hsig(s10)), __float2half(h1.y * hsig(s11))};
                *(__half2*)&g_a2f[erow * NU + colg] = a01;
                *(__half2*)&g_a2f[(erow + 8) * NU + colg] = a23;
            } else {                                        // z gate
                int j = colg - 1024;
                *(float2*)&g_z[erow * NU + j] = make_float2(hsig(s00), hsig(s01));
                *(float2*)&g_z[(erow + 8) * NU + j] = make_float2(hsig(s10), hsig(s11));
            }
        }
        grid_bar();
        // ---- stage full a2 ----
#pragma unroll
        for (int it = 0; it < 32; it++) {
            int slot = it * 256 + tid;
            int row = slot >> 7, grp = slot & 127;
            *(uint4*)(sm + row * SROW2 + grp * 8) = *(const uint4*)(g_a2f + row * NU + grp * 8);
        }
        __syncthreads();
        // ---- phase B: (h*r) @ U, cols bx*8..+8 (K split across ws), fused act_h ----
        {
            float acc[4] = {0.f, 0.f, 0.f, 0.f};
            const uint4* bfr = g_UcF + ((size_t)bx * 64) * 32 + lane;
#pragma unroll 8
            for (int kc = 0; kc < 32; kc++) {
                uint32_t a0, a1, a2, a3;
                int kk = ws * 32 + kc;
                LDSM_X4(a0, a1, a2, a3, aBase + kk * 32);
                uint4 bv = bfr[(size_t)kk * 32];
                MMA_F16(acc, a0, a1, a2, a3, bv.x, bv.y);
                MMA_F16(acc, a0, a1, a2, a3, bv.z, bv.w);
            }
            *(float2*)&red[((ws * 64) + erow) * 8 + ecol2] = make_float2(acc[0], acc[1]);
            *(float2*)&red[((ws * 64) + erow + 8) * 8 + ecol2] = make_float2(acc[2], acc[3]);
            __syncthreads();
#pragma unroll
            for (int o = tid; o < 512; o += 256) {
                int b = o >> 3, jj = o & 7;
                int j = bx * 8 + jj;
                float s = red[b * 8 + jj] + red[(64 + b) * 8 + jj]
                        + g_G[((size_t)t * NB + b) * N3 + 2048 + j];
                float hc = tanhf(s);
                float z = g_z[b * NU + j], h = g_h[b * NU + j];
                float hn = (1.0f - z) * h + z * hc;
                g_h[b * NU + j] = hn;
                g_hf[b * NU + j] = __float2half(hn);
                out[((size_t)b * NTT + t) * NU + j] = hn;
            }
        }
        grid_bar();
    }
}

// ------------------------- launch -------------------------------------------
#define REC_SMEM (64 * SROW2 * 2 + 4096)

extern "C" void kernel_launch(void* const* d_in, const int* in_sizes, int n_in,
                              void* d_out, int out_size) {
    const float* all = (const float*)d_in[0];
    const float* h0  = (const float*)d_in[1];
    const float* Wr  = (const float*)d_in[2];
    const float* Ur  = (const float*)d_in[3];
    const float* Cr  = (const float*)d_in[4];
    const float* Wz  = (const float*)d_in[5];
    const float* Uz  = (const float*)d_in[6];
    const float* Cz  = (const float*)d_in[7];
    const float* Wc  = (const float*)d_in[8];
    const float* Uc  = (const float*)d_in[9];
    const float* Cc  = (const float*)d_in[10];
    float* out = (float*)d_out;

    static int smem_set = 0;
    if (!smem_set) {
        cudaFuncSetAttribute(recurrent, cudaFuncAttributeMaxDynamicSharedMemorySize, REC_SMEM);
        smem_set = 1;
    }

    pack_AF<<<16384, 256>>>(all);
    pack_WF<<<6144, 256>>>(Wr, Cr, Wz, Cz, Wc, Cc);
    pack_UrzF<<<2048, 256>>>(Ur, Uz);
    pack_UcF<<<1024, 256>>>(Uc);
    pack_h_split<<<256, 256>>>(h0);
    gemm_pre_f<<<dim3(24, 128), 256>>>();
    recurrent<<<NBLK, 256, REC_SMEM>>>(out);
}

// round 10
// speedup vs baseline: 2.4991x; 1.2032x over previous
#include <cuda_runtime.h>
#include <cuda_bf16.h>
#include <cuda_fp16.h>
#include <math.h>
#include <stdint.h>

#define NB 64
#define NTT 256
#define NU 1024
#define KX 2048
#define N3 3072
#define NBLK 128

// ------------------------- device scratch (no allocs allowed) ----------------
__device__ __align__(16) uint4 g_AFh[(size_t)1024 * 128 * 32];  // A frag-major bf16 hi (64MB)
__device__ __align__(16) uint4 g_AFl[(size_t)1024 * 128 * 32];  // A frag-major bf16 lo (64MB)
__device__ __align__(16) uint4 g_WF[(size_t)384 * 128 * 32];    // W frag-major (24MB)
__device__ __align__(16) float g_G[(size_t)NTT * NB * N3];
__device__ __align__(16) uint4 g_UrzF[256 * 64 * 32];           // frag-packed [U_r|U_z] f16 hi/lo
__device__ __align__(16) uint4 g_UcF[128 * 64 * 32];            // frag-packed U f16 hi/lo
__device__ __align__(16) uint4 g_hF[4 * 64 * 32];               // h as f16 A-fragments (128KB)
__device__ __align__(16) uint4 g_a2F[4 * 64 * 32];              // a2 as f16 A-fragments
__device__ __align__(16) float g_h[NB * NU];
__device__ __align__(16) float g_z[NB * NU];

// grid barrier state (monotonic generation -> safe across graph replays)
__device__ unsigned g_cnt = 0;
__device__ unsigned g_gen = 0;

__device__ __forceinline__ void grid_bar() {
    __syncthreads();
    if (threadIdx.x == 0) {
        unsigned gen = *((volatile unsigned*)&g_gen);
        __threadfence();
        if (atomicAdd(&g_cnt, 1u) == NBLK - 1u) {
            g_cnt = 0;
            __threadfence();
            atomicAdd(&g_gen, 1u);
        } else {
            unsigned spins = 0;
            while (*((volatile unsigned*)&g_gen) == gen) {
                if (++spins > 4096u) __nanosleep(40);
                if (spins > 4000000u) break;   // safety valve: never hang
            }
        }
        __threadfence();
    }
    __syncthreads();
}

// ------------------------- mma.sync helpers (sm_80+ ISA) ---------------------
#define MMA_BF16(d, a0, a1, a2, a3, b0, b1) \
    asm volatile("mma.sync.aligned.m16n8k16.row.col.f32.bf16.bf16.f32 " \
                 "{%0,%1,%2,%3}, {%4,%5,%6,%7}, {%8,%9}, {%0,%1,%2,%3};" \
                 : "+f"((d)[0]), "+f"((d)[1]), "+f"((d)[2]), "+f"((d)[3]) \
                 : "r"(a0), "r"(a1), "r"(a2), "r"(a3), "r"(b0), "r"(b1))
#define MMA_F16(d, a0, a1, a2, a3, b0, b1) \
    asm volatile("mma.sync.aligned.m16n8k16.row.col.f32.f16.f16.f32 " \
                 "{%0,%1,%2,%3}, {%4,%5,%6,%7}, {%8,%9}, {%0,%1,%2,%3};" \
                 : "+f"((d)[0]), "+f"((d)[1]), "+f"((d)[2]), "+f"((d)[3]) \
                 : "r"(a0), "r"(a1), "r"(a2), "r"(a3), "r"(b0), "r"(b1))

static __device__ __forceinline__ uint32_t pack2hi(float x, float y) {
    __nv_bfloat162 v = {__float2bfloat16(x), __float2bfloat16(y)};
    return *(uint32_t*)&v;
}
static __device__ __forceinline__ uint32_t pack2lo(float x, float y) {
    float hx = __bfloat162float(__float2bfloat16(x));
    float hy = __bfloat162float(__float2bfloat16(y));
    __nv_bfloat162 v = {__float2bfloat16(x - hx), __float2bfloat16(y - hy)};
    return *(uint32_t*)&v;
}
static __device__ __forceinline__ uint32_t pack2hf(float x, float y) {
    __half2 v = {__float2half(x), __float2half(y)};
    return *(uint32_t*)&v;
}
static __device__ __forceinline__ uint32_t pack2lf(float x, float y) {
    float hx = __half2float(__float2half(x));
    float hy = __half2float(__float2half(y));
    __half2 v = {__float2half(x - hx), __float2half(y - hy)};
    return *(uint32_t*)&v;
}
static __device__ __forceinline__ float hsig(float x) {
    return fminf(fmaxf(0.2f * x + 0.5f, 0.0f), 1.0f);
}

// ------------------------- packing / init -----------------------------------
__global__ void pack_AF(const float* __restrict__ all) {
    int fid = blockIdx.x * blockDim.x + threadIdx.x;   // 4194304
    int lane = fid & 31, kc = (fid >> 5) & 127, m16t = fid >> 12;
    int row = m16t * 16 + (lane >> 2);
    int col = kc * 16 + (lane & 3) * 2;
    const float* p = all + (size_t)row * KX + col;
    float a00 = p[0], a01 = p[1];
    float a10 = p[8 * KX], a11 = p[8 * KX + 1];
    float a20 = p[8], a21 = p[9];
    float a30 = p[8 * KX + 8], a31 = p[8 * KX + 9];
    g_AFh[fid] = make_uint4(pack2hi(a00, a01), pack2hi(a10, a11),
                            pack2hi(a20, a21), pack2hi(a30, a31));
    g_AFl[fid] = make_uint4(pack2lo(a00, a01), pack2lo(a10, a11),
                            pack2lo(a20, a21), pack2lo(a30, a31));
}

__global__ void pack_WF(const float* __restrict__ Wr, const float* __restrict__ Cr,
                        const float* __restrict__ Wz, const float* __restrict__ Cz,
                        const float* __restrict__ Wc, const float* __restrict__ Cc) {
    int fid = blockIdx.x * blockDim.x + threadIdx.x;   // 1572864
    int lane = fid & 31, kc = (fid >> 5) & 127, n8t = fid >> 12;
    int n = n8t * 8 + (lane >> 2);
    int k0 = kc * 16 + (lane & 3) * 2;
    int sel = n >> 10, j = n & 1023;
    const float* C = (sel == 0) ? Cr : (sel == 1) ? Cz : Cc;
    const float* W = (sel == 0) ? Wr : (sel == 1) ? Wz : Wc;
    auto wat = [&](int k) -> float {
        return (k < 1024) ? C[k * NU + j] : W[(k - 1024) * NU + j];
    };
    float b00 = wat(k0), b01 = wat(k0 + 1);
    float b10 = wat(k0 + 8), b11 = wat(k0 + 9);
    g_WF[fid] = make_uint4(pack2hi(b00, b01), pack2hi(b10, b11),
                           pack2lo(b00, b01), pack2lo(b10, b11));
}

__global__ void pack_UrzF(const float* __restrict__ Ur, const float* __restrict__ Uz) {
    int fid = blockIdx.x * blockDim.x + threadIdx.x;   // 524288
    int nt = fid >> 11, kc = (fid >> 5) & 63, lane = fid & 31;
    int n = nt * 8 + (lane >> 2);
    int k0 = kc * 16 + (lane & 3) * 2;
    const float* src = (n < 1024) ? Ur : Uz;
    int nn = n & 1023;
    float v00 = src[(k0 + 0) * NU + nn], v01 = src[(k0 + 1) * NU + nn];
    float v10 = src[(k0 + 8) * NU + nn], v11 = src[(k0 + 9) * NU + nn];
    g_UrzF[fid] = make_uint4(pack2hf(v00, v01), pack2hf(v10, v11),
                             pack2lf(v00, v01), pack2lf(v10, v11));
}

__global__ void pack_UcF(const float* __restrict__ Uc) {
    int fid = blockIdx.x * blockDim.x + threadIdx.x;   // 262144
    int nt = fid >> 11, kc = (fid >> 5) & 63, lane = fid & 31;
    int n = nt * 8 + (lane >> 2);
    int k0 = kc * 16 + (lane & 3) * 2;
    float v00 = Uc[(k0 + 0) * NU + n], v01 = Uc[(k0 + 1) * NU + n];
    float v10 = Uc[(k0 + 8) * NU + n], v11 = Uc[(k0 + 9) * NU + n];
    g_UcF[fid] = make_uint4(pack2hf(v00, v01), pack2hf(v10, v11),
                            pack2lf(v00, v01), pack2lf(v10, v11));
}

__global__ void pack_h_init(const float* __restrict__ h0) {
    int i = blockIdx.x * blockDim.x + threadIdx.x;     // 65536
    if (i < NB * NU) g_h[i] = h0[i];
    if (i < 4 * 64 * 32) {                              // h fragments
        int lane = i & 31, kc = (i >> 5) & 63, m16t = i >> 11;
        int r0 = m16t * 16 + (lane >> 2);
        int c0 = kc * 16 + (lane & 3) * 2;
        g_hF[i] = make_uint4(
            pack2hf(h0[r0 * NU + c0],           h0[r0 * NU + c0 + 1]),
            pack2hf(h0[(r0 + 8) * NU + c0],     h0[(r0 + 8) * NU + c0 + 1]),
            pack2hf(h0[r0 * NU + c0 + 8],       h0[r0 * NU + c0 + 9]),
            pack2hf(h0[(r0 + 8) * NU + c0 + 8], h0[(r0 + 8) * NU + c0 + 9]));
    }
}

// ------------------------- frag-direct precompute GEMM (unchanged) -----------
__global__ __launch_bounds__(256) void gemm_pre_f() {
    const int tid = threadIdx.x;
    const int wid = tid >> 5, lane = tid & 31;
    const int wm = wid >> 2, wn = wid & 3;
    const int bn = blockIdx.x, bm = blockIdx.y;

    float acc[4][4][4];
#pragma unroll
    for (int i = 0; i < 4; i++)
#pragma unroll
        for (int j = 0; j < 4; j++)
#pragma unroll
            for (int k = 0; k < 4; k++) acc[i][j][k] = 0.0f;

    const uint4* ah = g_AFh + ((size_t)(bm * 8 + wm * 4) * 128) * 32 + lane;
    const uint4* al = g_AFl + ((size_t)(bm * 8 + wm * 4) * 128) * 32 + lane;
    const uint4* bp = g_WF  + ((size_t)(bn * 16 + wn * 4) * 128) * 32 + lane;

    for (int kc = 0; kc < 128; kc++) {
        uint4 af[4], alf[4], bf[4];
#pragma unroll
        for (int mi = 0; mi < 4; mi++) {
            af[mi]  = ah[(size_t)(mi * 128 + kc) * 32];
            alf[mi] = al[(size_t)(mi * 128 + kc) * 32];
        }
#pragma unroll
        for (int ni = 0; ni < 4; ni++) bf[ni] = bp[(size_t)(ni * 128 + kc) * 32];
#pragma unroll
        for (int mi = 0; mi < 4; mi++)
#pragma unroll
            for (int ni = 0; ni < 4; ni++)
                MMA_BF16(acc[mi][ni], af[mi].x, af[mi].y, af[mi].z, af[mi].w,
                         bf[ni].x, bf[ni].y);
#pragma unroll
        for (int mi = 0; mi < 4; mi++)
#pragma unroll
            for (int ni = 0; ni < 4; ni++)
                MMA_BF16(acc[mi][ni], af[mi].x, af[mi].y, af[mi].z, af[mi].w,
                         bf[ni].z, bf[ni].w);
#pragma unroll
        for (int mi = 0; mi < 4; mi++)
#pragma unroll
            for (int ni = 0; ni < 4; ni++)
                MMA_BF16(acc[mi][ni], alf[mi].x, alf[mi].y, alf[mi].z, alf[mi].w,
                         bf[ni].x, bf[ni].y);
    }

#pragma unroll
    for (int mi = 0; mi < 4; mi++) {
        int mA = bm * 128 + wm * 64 + mi * 16 + (lane >> 2);
        int mB = mA + 8;
        int bA = mA >> 8, tA = mA & 255;
        int bB = mB >> 8, tB = mB & 255;
        float* oA = g_G + (size_t)(tA * NB + bA) * N3;
        float* oB = g_G + (size_t)(tB * NB + bB) * N3;
        int colb = bn * 128 + wn * 32 + (lane & 3) * 2;
#pragma unroll
        for (int ni = 0; ni < 4; ni++) {
            int c = colb + ni * 8;
            *(float2*)(oA + c) = make_float2(acc[mi][ni][0], acc[mi][ni][1]);
            *(float2*)(oB + c) = make_float2(acc[mi][ni][2], acc[mi][ni][3]);
        }
    }
}

// ------------------------- persistent recurrent kernel (frag-direct) ---------
// 128 CTAs x 256 thr. h/a2 live as f16 A-fragments in global; epilogues write
// them directly (C-frag layout == A-frag layout). No smem staging, no LDSM.
__global__ __launch_bounds__(256, 1) void recurrent(float* __restrict__ out) {
    __shared__ __align__(16) float red[128 * 8];       // phase B k-half reduce (4KB)
    const int bx = blockIdx.x;
    const int tid = threadIdx.x;
    const int wid = tid >> 5, lane = tid & 31;
    const int wm = wid >> 1, ws = wid & 1;
    const int erow = wm * 16 + (lane >> 2);
    const int ecol2 = (lane & 3) * 2;
    const int eb = tid >> 2, ejp = tid & 3;            // phase B final mapping

    for (int t = 0; t < NTT; t++) {
        // ===== phase A: h @ [U_r|U_z], cols bx*16..+16, fused act_rz =========
        {
            const uint4* afr = g_hF + (wm * 64) * 32 + lane;
            const uint4* bfr = g_UrzF + ((size_t)(bx * 2 + ws) * 64) * 32 + lane;
            const int colg = bx * 16 + ws * 8 + ecol2;
            float2 G0 = *(const float2*)&g_G[((size_t)t * NB + erow) * N3 + colg];
            float2 G1 = *(const float2*)&g_G[((size_t)t * NB + erow + 8) * N3 + colg];
            float2 h0v = make_float2(0.f, 0.f), h1v = make_float2(0.f, 0.f);
            if (bx < 64) {
                h0v = __ldcg((const float2*)&g_h[erow * NU + colg]);
                h1v = __ldcg((const float2*)&g_h[(erow + 8) * NU + colg]);
            }
            float acc[4] = {0.f, 0.f, 0.f, 0.f};
#pragma unroll 8
            for (int kc = 0; kc < 64; kc++) {
                uint4 av = __ldcg(&afr[kc * 32]);
                uint4 bv = __ldg(&bfr[(size_t)kc * 32]);
                MMA_F16(acc, av.x, av.y, av.z, av.w, bv.x, bv.y);
                MMA_F16(acc, av.x, av.y, av.z, av.w, bv.z, bv.w);
            }
            float s00 = acc[0] + G0.x, s01 = acc[1] + G0.y;
            float s10 = acc[2] + G1.x, s11 = acc[3] + G1.y;
            if (bx < 64) {                              // r gate -> a2 frags
                float a0 = h0v.x * hsig(s00), a1 = h0v.y * hsig(s01);
                float a2v = h1v.x * hsig(s10), a3v = h1v.y * hsig(s11);
                uint2* dst = (uint2*)&g_a2F[(wm * 64 + bx) * 32 + lane];
                dst[ws] = make_uint2(pack2hf(a0, a1), pack2hf(a2v, a3v));
            } else {                                    // z gate
                int j = colg - 1024;
                *(float2*)&g_z[erow * NU + j] = make_float2(hsig(s00), hsig(s01));
                *(float2*)&g_z[(erow + 8) * NU + j] = make_float2(hsig(s10), hsig(s11));
            }
        }
        grid_bar();
        // ===== phase B: (h*r) @ U, cols bx*8..+8, fused act_h ================
        {
            const uint4* afr = g_a2F + (wm * 64) * 32 + lane;
            const uint4* bfr = g_UcF + ((size_t)bx * 64) * 32 + lane;
            const int j0 = bx * 8 + ejp * 2;
            float2 Gc = *(const float2*)&g_G[((size_t)t * NB + eb) * N3 + 2048 + j0];
            float2 zv = __ldcg((const float2*)&g_z[eb * NU + j0]);
            float2 hv = __ldcg((const float2*)&g_h[eb * NU + j0]);
            float acc[4] = {0.f, 0.f, 0.f, 0.f};
#pragma unroll 8
            for (int kc = 0; kc < 32; kc++) {
                int kk = ws * 32 + kc;
                uint4 av = __ldcg(&afr[kk * 32]);
                uint4 bv = __ldg(&bfr[(size_t)kk * 32]);
                MMA_F16(acc, av.x, av.y, av.z, av.w, bv.x, bv.y);
                MMA_F16(acc, av.x, av.y, av.z, av.w, bv.z, bv.w);
            }
            *(float2*)&red[(ws * 64 + erow) * 8 + ecol2] = make_float2(acc[0], acc[1]);
            *(float2*)&red[(ws * 64 + erow + 8) * 8 + ecol2] = make_float2(acc[2], acc[3]);
            __syncthreads();
            float s0 = red[eb * 8 + ejp * 2]     + red[(64 + eb) * 8 + ejp * 2]     + Gc.x;
            float s1 = red[eb * 8 + ejp * 2 + 1] + red[(64 + eb) * 8 + ejp * 2 + 1] + Gc.y;
            float hn0 = (1.0f - zv.x) * hv.x + zv.x * tanhf(s0);
            float hn1 = (1.0f - zv.y) * hv.y + zv.y * tanhf(s1);
            *(float2*)&g_h[eb * NU + j0] = make_float2(hn0, hn1);
            *(float2*)&out[((size_t)eb * NTT + t) * NU + j0] = make_float2(hn0, hn1);
            int comp = ((eb >> 3) & 1) | ((bx & 1) << 1);
            ((uint32_t*)&g_hF[((eb >> 4) * 64 + (bx >> 1)) * 32 + (((eb & 7) << 2) | ejp)])[comp]
                = pack2hf(hn0, hn1);
        }
        grid_bar();
    }
}

// ------------------------- launch -------------------------------------------
extern "C" void kernel_launch(void* const* d_in, const int* in_sizes, int n_in,
                              void* d_out, int out_size) {
    const float* all = (const float*)d_in[0];
    const float* h0  = (const float*)d_in[1];
    const float* Wr  = (const float*)d_in[2];
    const float* Ur  = (const float*)d_in[3];
    const float* Cr  = (const float*)d_in[4];
    const float* Wz  = (const float*)d_in[5];
    const float* Uz  = (const float*)d_in[6];
    const float* Cz  = (const float*)d_in[7];
    const float* Wc  = (const float*)d_in[8];
    const float* Uc  = (const float*)d_in[9];
    const float* Cc  = (const float*)d_in[10];
    float* out = (float*)d_out;

    pack_AF<<<16384, 256>>>(all);
    pack_WF<<<6144, 256>>>(Wr, Cr, Wz, Cz, Wc, Cc);
    pack_UrzF<<<2048, 256>>>(Ur, Uz);
    pack_UcF<<<1024, 256>>>(Uc);
    pack_h_init<<<256, 256>>>(h0);
    gemm_pre_f<<<dim3(24, 128), 256>>>();
    recurrent<<<NBLK, 256>>>(out);
}

// round 12
// speedup vs baseline: 2.5476x; 1.0194x over previous
#include <cuda_runtime.h>
#include <cuda_bf16.h>
#include <cuda_fp16.h>
#include <math.h>
#include <stdint.h>

#define NB 64
#define NTT 256
#define NU 1024
#define KX 2048
#define N3 3072
#define NBLK 128

// ------------------------- device scratch (no allocs allowed) ----------------
__device__ __align__(16) uint4 g_AF[(size_t)1024 * 128 * 32];   // A frag-major f16 (64MB)
__device__ __align__(16) uint2 g_WF[(size_t)384 * 128 * 32];    // W frag-major f16 (12.6MB)
__device__ __align__(16) float g_G[(size_t)NTT * NB * N3];
__device__ __align__(16) uint4 g_UrzF[256 * 64 * 32];           // frag-packed [U_r|U_z] f16 hi/lo
__device__ __align__(16) uint4 g_UcF[128 * 64 * 32];            // frag-packed U f16 hi/lo
__device__ __align__(16) uint4 g_hF[4 * 64 * 32];               // h as f16 A-fragments (128KB)
__device__ __align__(16) uint4 g_a2F[4 * 64 * 32];              // a2 as f16 A-fragments
__device__ __align__(16) float g_h[NB * NU];
__device__ __align__(16) float g_z[NB * NU];

// grid barrier state (monotonic generation -> safe across graph replays)
__device__ unsigned g_cnt = 0;
__device__ unsigned g_gen = 0;

__device__ __forceinline__ void grid_bar() {
    __syncthreads();
    if (threadIdx.x == 0) {
        unsigned gen = *((volatile unsigned*)&g_gen);
        __threadfence();
        if (atomicAdd(&g_cnt, 1u) == NBLK - 1u) {
            g_cnt = 0;
            __threadfence();
            atomicAdd(&g_gen, 1u);
        } else {
            unsigned spins = 0;
            while (*((volatile unsigned*)&g_gen) == gen) {
                if (++spins > 4096u) __nanosleep(40);
                if (spins > 4000000u) break;   // safety valve: never hang
            }
        }
        __threadfence();
    }
    __syncthreads();
}

// ------------------------- mma.sync helpers (sm_80+ ISA) ---------------------
#define MMA_F16(d, a0, a1, a2, a3, b0, b1) \
    asm volatile("mma.sync.aligned.m16n8k16.row.col.f32.f16.f16.f32 " \
                 "{%0,%1,%2,%3}, {%4,%5,%6,%7}, {%8,%9}, {%0,%1,%2,%3};" \
                 : "+f"((d)[0]), "+f"((d)[1]), "+f"((d)[2]), "+f"((d)[3]) \
                 : "r"(a0), "r"(a1), "r"(a2), "r"(a3), "r"(b0), "r"(b1))

static __device__ __forceinline__ uint32_t pack2hf(float x, float y) {
    __half2 v = {__float2half(x), __float2half(y)};
    return *(uint32_t*)&v;
}
static __device__ __forceinline__ uint32_t pack2lf(float x, float y) {
    float hx = __half2float(__float2half(x));
    float hy = __half2float(__float2half(y));
    __half2 v = {__float2half(x - hx), __float2half(y - hy)};
    return *(uint32_t*)&v;
}
static __device__ __forceinline__ float hsig(float x) {
    return fminf(fmaxf(0.2f * x + 0.5f, 0.0f), 1.0f);
}

// ------------------------- packing / init -----------------------------------
// A fragment layout (m16n8k16 .row A): lane l -> row=(l>>2), col=(l&3)*2
__global__ void pack_AF(const float* __restrict__ all) {
    int fid = blockIdx.x * blockDim.x + threadIdx.x;   // 4194304
    int lane = fid & 31, kc = (fid >> 5) & 127, m16t = fid >> 12;
    int row = m16t * 16 + (lane >> 2);
    int col = kc * 16 + (lane & 3) * 2;
    const float* p = all + (size_t)row * KX + col;
    g_AF[fid] = make_uint4(pack2hf(p[0], p[1]),
                           pack2hf(p[8 * KX], p[8 * KX + 1]),
                           pack2hf(p[8], p[9]),
                           pack2hf(p[8 * KX + 8], p[8 * KX + 9]));
}

// W fragment layout (.col B): lane l -> n=(l>>2), k=(l&3)*2
__global__ void pack_WF(const float* __restrict__ Wr, const float* __restrict__ Cr,
                        const float* __restrict__ Wz, const float* __restrict__ Cz,
                        const float* __restrict__ Wc, const float* __restrict__ Cc) {
    int fid = blockIdx.x * blockDim.x + threadIdx.x;   // 1572864
    int lane = fid & 31, kc = (fid >> 5) & 127, n8t = fid >> 12;
    int n = n8t * 8 + (lane >> 2);
    int k0 = kc * 16 + (lane & 3) * 2;
    int sel = n >> 10, j = n & 1023;
    const float* C = (sel == 0) ? Cr : (sel == 1) ? Cz : Cc;
    const float* W = (sel == 0) ? Wr : (sel == 1) ? Wz : Wc;
    auto wat = [&](int k) -> float {
        return (k < 1024) ? C[k * NU + j] : W[(k - 1024) * NU + j];
    };
    g_WF[fid] = make_uint2(pack2hf(wat(k0), wat(k0 + 1)),
                           pack2hf(wat(k0 + 8), wat(k0 + 9)));
}

__global__ void pack_UrzF(const float* __restrict__ Ur, const float* __restrict__ Uz) {
    int fid = blockIdx.x * blockDim.x + threadIdx.x;   // 524288
    int nt = fid >> 11, kc = (fid >> 5) & 63, lane = fid & 31;
    int n = nt * 8 + (lane >> 2);
    int k0 = kc * 16 + (lane & 3) * 2;
    const float* src = (n < 1024) ? Ur : Uz;
    int nn = n & 1023;
    float v00 = src[(k0 + 0) * NU + nn], v01 = src[(k0 + 1) * NU + nn];
    float v10 = src[(k0 + 8) * NU + nn], v11 = src[(k0 + 9) * NU + nn];
    g_UrzF[fid] = make_uint4(pack2hf(v00, v01), pack2hf(v10, v11),
                             pack2lf(v00, v01), pack2lf(v10, v11));
}

__global__ void pack_UcF(const float* __restrict__ Uc) {
    int fid = blockIdx.x * blockDim.x + threadIdx.x;   // 262144
    int nt = fid >> 11, kc = (fid >> 5) & 63, lane = fid & 31;
    int n = nt * 8 + (lane >> 2);
    int k0 = kc * 16 + (lane & 3) * 2;
    float v00 = Uc[(k0 + 0) * NU + n], v01 = Uc[(k0 + 1) * NU + n];
    float v10 = Uc[(k0 + 8) * NU + n], v11 = Uc[(k0 + 9) * NU + n];
    g_UcF[fid] = make_uint4(pack2hf(v00, v01), pack2hf(v10, v11),
                            pack2lf(v00, v01), pack2lf(v10, v11));
}

__global__ void pack_h_init(const float* __restrict__ h0) {
    int i = blockIdx.x * blockDim.x + threadIdx.x;     // 65536
    if (i < NB * NU) g_h[i] = h0[i];
    if (i < 4 * 64 * 32) {                              // h fragments
        int lane = i & 31, kc = (i >> 5) & 63, m16t = i >> 11;
        int r0 = m16t * 16 + (lane >> 2);
        int c0 = kc * 16 + (lane & 3) * 2;
        g_hF[i] = make_uint4(
            pack2hf(h0[r0 * NU + c0],           h0[r0 * NU + c0 + 1]),
            pack2hf(h0[(r0 + 8) * NU + c0],     h0[(r0 + 8) * NU + c0 + 1]),
            pack2hf(h0[r0 * NU + c0 + 8],       h0[r0 * NU + c0 + 9]),
            pack2hf(h0[(r0 + 8) * NU + c0 + 8], h0[(r0 + 8) * NU + c0 + 9]));
    }
}

// ------------------------- frag-direct precompute GEMM (single f16) ----------
// C[16384,3072] = A@W, plain f16 inputs, fp32 accum. grid (24 bn, 128 bm),
// 8 warps: wm (2) x wn (4); warp tile 64x32; 16 MMAs per kc.
__global__ __launch_bounds__(256) void gemm_pre_f() {
    const int tid = threadIdx.x;
    const int wid = tid >> 5, lane = tid & 31;
    const int wm = wid >> 2, wn = wid & 3;
    const int bn = blockIdx.x, bm = blockIdx.y;

    float acc[4][4][4];
#pragma unroll
    for (int i = 0; i < 4; i++)
#pragma unroll
        for (int j = 0; j < 4; j++)
#pragma unroll
            for (int k = 0; k < 4; k++) acc[i][j][k] = 0.0f;

    const uint4* ap = g_AF + ((size_t)(bm * 8 + wm * 4) * 128) * 32 + lane;
    const uint2* bp = g_WF + ((size_t)(bn * 16 + wn * 4) * 128) * 32 + lane;

    for (int kc = 0; kc < 128; kc++) {
        uint4 af[4];
        uint2 bf[4];
#pragma unroll
        for (int mi = 0; mi < 4; mi++) af[mi] = ap[(size_t)(mi * 128 + kc) * 32];
#pragma unroll
        for (int ni = 0; ni < 4; ni++) bf[ni] = bp[(size_t)(ni * 128 + kc) * 32];
#pragma unroll
        for (int mi = 0; mi < 4; mi++)
#pragma unroll
            for (int ni = 0; ni < 4; ni++)
                MMA_F16(acc[mi][ni], af[mi].x, af[mi].y, af[mi].z, af[mi].w,
                        bf[ni].x, bf[ni].y);
    }

#pragma unroll
    for (int mi = 0; mi < 4; mi++) {
        int mA = bm * 128 + wm * 64 + mi * 16 + (lane >> 2);
        int mB = mA + 8;
        int bA = mA >> 8, tA = mA & 255;
        int bB = mB >> 8, tB = mB & 255;
        float* oA = g_G + (size_t)(tA * NB + bA) * N3;
        float* oB = g_G + (size_t)(tB * NB + bB) * N3;
        int colb = bn * 128 + wn * 32 + (lane & 3) * 2;
#pragma unroll
        for (int ni = 0; ni < 4; ni++) {
            int c = colb + ni * 8;
            *(float2*)(oA + c) = make_float2(acc[mi][ni][0], acc[mi][ni][1]);
            *(float2*)(oB + c) = make_float2(acc[mi][ni][2], acc[mi][ni][3]);
        }
    }
}

// ------------------------- persistent recurrent kernel (frag-direct) ---------
// UNCHANGED from the passing R10 kernel.
__global__ __launch_bounds__(256, 1) void recurrent(float* __restrict__ out) {
    __shared__ __align__(16) float red[128 * 8];       // phase B k-half reduce (4KB)
    const int bx = blockIdx.x;
    const int tid = threadIdx.x;
    const int wid = tid >> 5, lane = tid & 31;
    const int wm = wid >> 1, ws = wid & 1;
    const int erow = wm * 16 + (lane >> 2);
    const int ecol2 = (lane & 3) * 2;
    const int eb = tid >> 2, ejp = tid & 3;            // phase B final mapping

    for (int t = 0; t < NTT; t++) {
        // ===== phase A: h @ [U_r|U_z], cols bx*16..+16, fused act_rz =========
        {
            const uint4* afr = g_hF + (wm * 64) * 32 + lane;
            const uint4* bfr = g_UrzF + ((size_t)(bx * 2 + ws) * 64) * 32 + lane;
            const int colg = bx * 16 + ws * 8 + ecol2;
            float2 G0 = *(const float2*)&g_G[((size_t)t * NB + erow) * N3 + colg];
            float2 G1 = *(const float2*)&g_G[((size_t)t * NB + erow + 8) * N3 + colg];
            float2 h0v = make_float2(0.f, 0.f), h1v = make_float2(0.f, 0.f);
            if (bx < 64) {
                h0v = __ldcg((const float2*)&g_h[erow * NU + colg]);
                h1v = __ldcg((const float2*)&g_h[(erow + 8) * NU + colg]);
            }
            float acc[4] = {0.f, 0.f, 0.f, 0.f};
#pragma unroll 8
            for (int kc = 0; kc < 64; kc++) {
                uint4 av = __ldcg(&afr[kc * 32]);
                uint4 bv = __ldg(&bfr[(size_t)kc * 32]);
                MMA_F16(acc, av.x, av.y, av.z, av.w, bv.x, bv.y);
                MMA_F16(acc, av.x, av.y, av.z, av.w, bv.z, bv.w);
            }
            float s00 = acc[0] + G0.x, s01 = acc[1] + G0.y;
            float s10 = acc[2] + G1.x, s11 = acc[3] + G1.y;
            if (bx < 64) {                              // r gate -> a2 frags
                float a0 = h0v.x * hsig(s00), a1 = h0v.y * hsig(s01);
                float a2v = h1v.x * hsig(s10), a3v = h1v.y * hsig(s11);
                uint2* dst = (uint2*)&g_a2F[(wm * 64 + bx) * 32 + lane];
                dst[ws] = make_uint2(pack2hf(a0, a1), pack2hf(a2v, a3v));
            } else {                                    // z gate
                int j = colg - 1024;
                *(float2*)&g_z[erow * NU + j] = make_float2(hsig(s00), hsig(s01));
                *(float2*)&g_z[(erow + 8) * NU + j] = make_float2(hsig(s10), hsig(s11));
            }
        }
        grid_bar();
        // ===== phase B: (h*r) @ U, cols bx*8..+8, fused act_h ================
        {
            const uint4* afr = g_a2F + (wm * 64) * 32 + lane;
            const uint4* bfr = g_UcF + ((size_t)bx * 64) * 32 + lane;
            const int j0 = bx * 8 + ejp * 2;
            float2 Gc = *(const float2*)&g_G[((size_t)t * NB + eb) * N3 + 2048 + j0];
            float2 zv = __ldcg((const float2*)&g_z[eb * NU + j0]);
            float2 hv = __ldcg((const float2*)&g_h[eb * NU + j0]);
            float acc[4] = {0.f, 0.f, 0.f, 0.f};
#pragma unroll 8
            for (int kc = 0; kc < 32; kc++) {
                int kk = ws * 32 + kc;
                uint4 av = __ldcg(&afr[kk * 32]);
                uint4 bv = __ldg(&bfr[(size_t)kk * 32]);
                MMA_F16(acc, av.x, av.y, av.z, av.w, bv.x, bv.y);
                MMA_F16(acc, av.x, av.y, av.z, av.w, bv.z, bv.w);
            }
            *(float2*)&red[(ws * 64 + erow) * 8 + ecol2] = make_float2(acc[0], acc[1]);
            *(float2*)&red[(ws * 64 + erow + 8) * 8 + ecol2] = make_float2(acc[2], acc[3]);
            __syncthreads();
            float s0 = red[eb * 8 + ejp * 2]     + red[(64 + eb) * 8 + ejp * 2]     + Gc.x;
            float s1 = red[eb * 8 + ejp * 2 + 1] + red[(64 + eb) * 8 + ejp * 2 + 1] + Gc.y;
            float hn0 = (1.0f - zv.x) * hv.x + zv.x * tanhf(s0);
            float hn1 = (1.0f - zv.y) * hv.y + zv.y * tanhf(s1);
            *(float2*)&g_h[eb * NU + j0] = make_float2(hn0, hn1);
            *(float2*)&out[((size_t)eb * NTT + t) * NU + j0] = make_float2(hn0, hn1);
            int comp = ((eb >> 3) & 1) | ((bx & 1) << 1);
            ((uint32_t*)&g_hF[((eb >> 4) * 64 + (bx >> 1)) * 32 + (((eb & 7) << 2) | ejp)])[comp]
                = pack2hf(hn0, hn1);
        }
        grid_bar();
    }
}

// ------------------------- launch -------------------------------------------
extern "C" void kernel_launch(void* const* d_in, const int* in_sizes, int n_in,
                              void* d_out, int out_size) {
    const float* all = (const float*)d_in[0];
    const float* h0  = (const float*)d_in[1];
    const float* Wr  = (const float*)d_in[2];
    const float* Ur  = (const float*)d_in[3];
    const float* Cr  = (const float*)d_in[4];
    const float* Wz  = (const float*)d_in[5];
    const float* Uz  = (const float*)d_in[6];
    const float* Cz  = (const float*)d_in[7];
    const float* Wc  = (const float*)d_in[8];
    const float* Uc  = (const float*)d_in[9];
    const float* Cc  = (const float*)d_in[10];
    float* out = (float*)d_out;

    pack_AF<<<16384, 256>>>(all);
    pack_WF<<<6144, 256>>>(Wr, Cr, Wz, Cz, Wc, Cc);
    pack_UrzF<<<2048, 256>>>(Ur, Uz);
    pack_UcF<<<1024, 256>>>(Uc);
    pack_h_init<<<256, 256>>>(h0);
    gemm_pre_f<<<dim3(24, 128), 256>>>();
    recurrent<<<NBLK, 256>>>(out);
}

// round 13
// speedup vs baseline: 2.7302x; 1.0717x over previous
#include <cuda_runtime.h>
#include <cuda_bf16.h>
#include <cuda_fp16.h>
#include <math.h>
#include <stdint.h>

#define NB 64
#define NTT 256
#define NU 1024
#define KX 2048
#define N3 3072
#define NBLK 128

// ------------------------- device scratch (no allocs allowed) ----------------
__device__ __align__(16) uint4 g_AF[(size_t)1024 * 128 * 32];   // A frag-major f16 (64MB)
__device__ __align__(16) uint2 g_WF[(size_t)384 * 128 * 32];    // W frag-major f16 (12.6MB)
__device__ __align__(16) float g_G[(size_t)NTT * NB * N3];
__device__ __align__(16) uint4 g_UrzF[256 * 64 * 32];           // frag-packed [U_r|U_z] f16 hi/lo
__device__ __align__(16) uint4 g_UcF[128 * 64 * 32];            // frag-packed U f16 hi/lo
__device__ __align__(16) uint4 g_hF[4 * 64 * 32];               // h as f16 A-fragments (128KB)
__device__ __align__(16) uint4 g_a2F[4 * 64 * 32];              // a2 as f16 A-fragments
__device__ __align__(16) float g_h[NB * NU];
__device__ __align__(16) float g_z[NB * NU];

// grid barrier state (monotonic generation -> safe across graph replays)
__device__ unsigned g_cnt = 0;
__device__ unsigned g_gen = 0;

__device__ __forceinline__ void grid_bar() {
    __syncthreads();
    if (threadIdx.x == 0) {
        unsigned gen = *((volatile unsigned*)&g_gen);
        __threadfence();
        if (atomicAdd(&g_cnt, 1u) == NBLK - 1u) {
            g_cnt = 0;
            __threadfence();
            atomicAdd(&g_gen, 1u);
        } else {
            unsigned spins = 0;
            while (*((volatile unsigned*)&g_gen) == gen) {
                if (++spins > 4096u) __nanosleep(40);
                if (spins > 4000000u) break;   // safety valve: never hang
            }
        }
        __threadfence();
    }
    __syncthreads();
}

// ------------------------- mma.sync helpers (sm_80+ ISA) ---------------------
#define MMA_F16(d, a0, a1, a2, a3, b0, b1) \
    asm volatile("mma.sync.aligned.m16n8k16.row.col.f32.f16.f16.f32 " \
                 "{%0,%1,%2,%3}, {%4,%5,%6,%7}, {%8,%9}, {%0,%1,%2,%3};" \
                 : "+f"((d)[0]), "+f"((d)[1]), "+f"((d)[2]), "+f"((d)[3]) \
                 : "r"(a0), "r"(a1), "r"(a2), "r"(a3), "r"(b0), "r"(b1))

static __device__ __forceinline__ uint32_t pack2hf(float x, float y) {
    __half2 v = {__float2half(x), __float2half(y)};
    return *(uint32_t*)&v;
}
static __device__ __forceinline__ uint32_t pack2lf(float x, float y) {
    float hx = __half2float(__float2half(x));
    float hy = __half2float(__float2half(y));
    __half2 v = {__float2half(x - hx), __float2half(y - hy)};
    return *(uint32_t*)&v;
}
static __device__ __forceinline__ float hsig(float x) {
    return fminf(fmaxf(0.2f * x + 0.5f, 0.0f), 1.0f);
}

// ------------------------- packing / init -----------------------------------
__global__ void pack_AF(const float* __restrict__ all) {
    int fid = blockIdx.x * blockDim.x + threadIdx.x;   // 4194304
    int lane = fid & 31, kc = (fid >> 5) & 127, m16t = fid >> 12;
    int row = m16t * 16 + (lane >> 2);
    int col = kc * 16 + (lane & 3) * 2;
    const float* p = all + (size_t)row * KX + col;
    g_AF[fid] = make_uint4(pack2hf(p[0], p[1]),
                           pack2hf(p[8 * KX], p[8 * KX + 1]),
                           pack2hf(p[8], p[9]),
                           pack2hf(p[8 * KX + 8], p[8 * KX + 9]));
}

__global__ void pack_WF(const float* __restrict__ Wr, const float* __restrict__ Cr,
                        const float* __restrict__ Wz, const float* __restrict__ Cz,
                        const float* __restrict__ Wc, const float* __restrict__ Cc) {
    int fid = blockIdx.x * blockDim.x + threadIdx.x;   // 1572864
    int lane = fid & 31, kc = (fid >> 5) & 127, n8t = fid >> 12;
    int n = n8t * 8 + (lane >> 2);
    int k0 = kc * 16 + (lane & 3) * 2;
    int sel = n >> 10, j = n & 1023;
    const float* C = (sel == 0) ? Cr : (sel == 1) ? Cz : Cc;
    const float* W = (sel == 0) ? Wr : (sel == 1) ? Wz : Wc;
    auto wat = [&](int k) -> float {
        return (k < 1024) ? C[k * NU + j] : W[(k - 1024) * NU + j];
    };
    g_WF[fid] = make_uint2(pack2hf(wat(k0), wat(k0 + 1)),
                           pack2hf(wat(k0 + 8), wat(k0 + 9)));
}

__global__ void pack_UrzF(const float* __restrict__ Ur, const float* __restrict__ Uz) {
    int fid = blockIdx.x * blockDim.x + threadIdx.x;   // 524288
    int nt = fid >> 11, kc = (fid >> 5) & 63, lane = fid & 31;
    int n = nt * 8 + (lane >> 2);
    int k0 = kc * 16 + (lane & 3) * 2;
    const float* src = (n < 1024) ? Ur : Uz;
    int nn = n & 1023;
    float v00 = src[(k0 + 0) * NU + nn], v01 = src[(k0 + 1) * NU + nn];
    float v10 = src[(k0 + 8) * NU + nn], v11 = src[(k0 + 9) * NU + nn];
    g_UrzF[fid] = make_uint4(pack2hf(v00, v01), pack2hf(v10, v11),
                             pack2lf(v00, v01), pack2lf(v10, v11));
}

__global__ void pack_UcF(const float* __restrict__ Uc) {
    int fid = blockIdx.x * blockDim.x + threadIdx.x;   // 262144
    int nt = fid >> 11, kc = (fid >> 5) & 63, lane = fid & 31;
    int n = nt * 8 + (lane >> 2);
    int k0 = kc * 16 + (lane & 3) * 2;
    float v00 = Uc[(k0 + 0) * NU + n], v01 = Uc[(k0 + 1) * NU + n];
    float v10 = Uc[(k0 + 8) * NU + n], v11 = Uc[(k0 + 9) * NU + n];
    g_UcF[fid] = make_uint4(pack2hf(v00, v01), pack2hf(v10, v11),
                            pack2lf(v00, v01), pack2lf(v10, v11));
}

__global__ void pack_h_init(const float* __restrict__ h0) {
    int i = blockIdx.x * blockDim.x + threadIdx.x;     // 65536
    if (i < NB * NU) g_h[i] = h0[i];
    if (i < 4 * 64 * 32) {                              // h fragments
        int lane = i & 31, kc = (i >> 5) & 63, m16t = i >> 11;
        int r0 = m16t * 16 + (lane >> 2);
        int c0 = kc * 16 + (lane & 3) * 2;
        g_hF[i] = make_uint4(
            pack2hf(h0[r0 * NU + c0],           h0[r0 * NU + c0 + 1]),
            pack2hf(h0[(r0 + 8) * NU + c0],     h0[(r0 + 8) * NU + c0 + 1]),
            pack2hf(h0[r0 * NU + c0 + 8],       h0[r0 * NU + c0 + 9]),
            pack2hf(h0[(r0 + 8) * NU + c0 + 8], h0[(r0 + 8) * NU + c0 + 9]));
    }
}

// ------------------------- frag-direct precompute GEMM (single f16) ----------
__global__ __launch_bounds__(256) void gemm_pre_f() {
    const int tid = threadIdx.x;
    const int wid = tid >> 5, lane = tid & 31;
    const int wm = wid >> 2, wn = wid & 3;
    const int bn = blockIdx.x, bm = blockIdx.y;

    float acc[4][4][4];
#pragma unroll
    for (int i = 0; i < 4; i++)
#pragma unroll
        for (int j = 0; j < 4; j++)
#pragma unroll
            for (int k = 0; k < 4; k++) acc[i][j][k] = 0.0f;

    const uint4* ap = g_AF + ((size_t)(bm * 8 + wm * 4) * 128) * 32 + lane;
    const uint2* bp = g_WF + ((size_t)(bn * 16 + wn * 4) * 128) * 32 + lane;

    for (int kc = 0; kc < 128; kc++) {
        uint4 af[4];
        uint2 bf[4];
#pragma unroll
        for (int mi = 0; mi < 4; mi++) af[mi] = ap[(size_t)(mi * 128 + kc) * 32];
#pragma unroll
        for (int ni = 0; ni < 4; ni++) bf[ni] = bp[(size_t)(ni * 128 + kc) * 32];
#pragma unroll
        for (int mi = 0; mi < 4; mi++)
#pragma unroll
            for (int ni = 0; ni < 4; ni++)
                MMA_F16(acc[mi][ni], af[mi].x, af[mi].y, af[mi].z, af[mi].w,
                        bf[ni].x, bf[ni].y);
    }

#pragma unroll
    for (int mi = 0; mi < 4; mi++) {
        int mA = bm * 128 + wm * 64 + mi * 16 + (lane >> 2);
        int mB = mA + 8;
        int bA = mA >> 8, tA = mA & 255;
        int bB = mB >> 8, tB = mB & 255;
        float* oA = g_G + (size_t)(tA * NB + bA) * N3;
        float* oB = g_G + (size_t)(tB * NB + bB) * N3;
        int colb = bn * 128 + wn * 32 + (lane & 3) * 2;
#pragma unroll
        for (int ni = 0; ni < 4; ni++) {
            int c = colb + ni * 8;
            *(float2*)(oA + c) = make_float2(acc[mi][ni][0], acc[mi][ni][1]);
            *(float2*)(oB + c) = make_float2(acc[mi][ni][2], acc[mi][ni][3]);
        }
    }
}

// ------------------------- persistent recurrent kernel (frag-direct) ---------
// Phase A now K-split across ws (halves h-frag L2 traffic) with smem reduce;
// split accumulators break HMMA dependency chains. Epilogue mappings unchanged.
__global__ __launch_bounds__(256, 1) void recurrent(float* __restrict__ out) {
    __shared__ __align__(16) float sred[2048];         // 8KB: A-reduce(16x128) / B-reduce(1024)
    const int bx = blockIdx.x;
    const int tid = threadIdx.x;
    const int wid = tid >> 5, lane = tid & 31;
    const int wm = wid >> 1, ws = wid & 1;
    const int erow = wm * 16 + (lane >> 2);
    const int ecol2 = (lane & 3) * 2;
    const int eb = tid >> 2, ejp = tid & 3;            // phase B final mapping

    for (int t = 0; t < NTT; t++) {
        // ===== phase A: h @ [U_r|U_z], cols bx*16..+16, K-split over ws ======
        {
            const uint4* afr = g_hF + (wm * 64) * 32 + lane;
            const uint4* b0  = g_UrzF + ((size_t)(bx * 2 + 0) * 64) * 32 + lane;
            const uint4* b1  = g_UrzF + ((size_t)(bx * 2 + 1) * 64) * 32 + lane;
            const int colg = bx * 16 + ws * 8 + ecol2;
            float2 G0 = *(const float2*)&g_G[((size_t)t * NB + erow) * N3 + colg];
            float2 G1 = *(const float2*)&g_G[((size_t)t * NB + erow + 8) * N3 + colg];
            float2 h0v = make_float2(0.f, 0.f), h1v = make_float2(0.f, 0.f);
            if (bx < 64) {
                h0v = __ldcg((const float2*)&g_h[erow * NU + colg]);
                h1v = __ldcg((const float2*)&g_h[(erow + 8) * NU + colg]);
            }
            float a0h[4] = {0.f, 0.f, 0.f, 0.f}, a0l[4] = {0.f, 0.f, 0.f, 0.f};
            float a1h[4] = {0.f, 0.f, 0.f, 0.f}, a1l[4] = {0.f, 0.f, 0.f, 0.f};
#pragma unroll 4
            for (int kc = 0; kc < 32; kc++) {
                int kk = ws * 32 + kc;
                uint4 av = __ldcg(&afr[kk * 32]);
                uint4 v0 = __ldg(&b0[(size_t)kk * 32]);
                uint4 v1 = __ldg(&b1[(size_t)kk * 32]);
                MMA_F16(a0h, av.x, av.y, av.z, av.w, v0.x, v0.y);
                MMA_F16(a0l, av.x, av.y, av.z, av.w, v0.z, v0.w);
                MMA_F16(a1h, av.x, av.y, av.z, av.w, v1.x, v1.y);
                MMA_F16(a1l, av.x, av.y, av.z, av.w, v1.z, v1.w);
            }
            // partial sums -> smem: slot = ((wm*2+nt)*2 + kshalf)
            *(float4*)&sred[((wm * 2 + 0) * 2 + ws) * 128 + lane * 4] =
                make_float4(a0h[0] + a0l[0], a0h[1] + a0l[1],
                            a0h[2] + a0l[2], a0h[3] + a0l[3]);
            *(float4*)&sred[((wm * 2 + 1) * 2 + ws) * 128 + lane * 4] =
                make_float4(a1h[0] + a1l[0], a1h[1] + a1l[1],
                            a1h[2] + a1l[2], a1h[3] + a1l[3]);
            __syncthreads();
            // epilogue: warp (wm, ws) owns n8 tile nt=ws (mapping as R10/R12)
            float4 p0 = *(const float4*)&sred[((wm * 2 + ws) * 2 + 0) * 128 + lane * 4];
            float4 p1 = *(const float4*)&sred[((wm * 2 + ws) * 2 + 1) * 128 + lane * 4];
            float s00 = p0.x + p1.x + G0.x, s01 = p0.y + p1.y + G0.y;
            float s10 = p0.z + p1.z + G1.x, s11 = p0.w + p1.w + G1.y;
            if (bx < 64) {                              // r gate -> a2 frags
                float a0 = h0v.x * hsig(s00), a1 = h0v.y * hsig(s01);
                float a2v = h1v.x * hsig(s10), a3v = h1v.y * hsig(s11);
                uint2* dst = (uint2*)&g_a2F[(wm * 64 + bx) * 32 + lane];
                dst[ws] = make_uint2(pack2hf(a0, a1), pack2hf(a2v, a3v));
            } else {                                    // z gate
                int j = colg - 1024;
                *(float2*)&g_z[erow * NU + j] = make_float2(hsig(s00), hsig(s01));
                *(float2*)&g_z[(erow + 8) * NU + j] = make_float2(hsig(s10), hsig(s11));
            }
        }
        grid_bar();
        // ===== phase B: (h*r) @ U, cols bx*8..+8, fused act_h ================
        {
            const uint4* afr = g_a2F + (wm * 64) * 32 + lane;
            const uint4* bfr = g_UcF + ((size_t)bx * 64) * 32 + lane;
            const int j0 = bx * 8 + ejp * 2;
            float2 Gc = *(const float2*)&g_G[((size_t)t * NB + eb) * N3 + 2048 + j0];
            float2 zv = __ldcg((const float2*)&g_z[eb * NU + j0]);
            float2 hv = __ldcg((const float2*)&g_h[eb * NU + j0]);
            float ach[4] = {0.f, 0.f, 0.f, 0.f}, acl[4] = {0.f, 0.f, 0.f, 0.f};
#pragma unroll 8
            for (int kc = 0; kc < 32; kc++) {
                int kk = ws * 32 + kc;
                uint4 av = __ldcg(&afr[kk * 32]);
                uint4 bv = __ldg(&bfr[(size_t)kk * 32]);
                MMA_F16(ach, av.x, av.y, av.z, av.w, bv.x, bv.y);
                MMA_F16(acl, av.x, av.y, av.z, av.w, bv.z, bv.w);
            }
            *(float2*)&sred[(ws * 64 + erow) * 8 + ecol2] =
                make_float2(ach[0] + acl[0], ach[1] + acl[1]);
            *(float2*)&sred[(ws * 64 + erow + 8) * 8 + ecol2] =
                make_float2(ach[2] + acl[2], ach[3] + acl[3]);
            __syncthreads();
            float s0 = sred[eb * 8 + ejp * 2]     + sred[(64 + eb) * 8 + ejp * 2]     + Gc.x;
            float s1 = sred[eb * 8 + ejp * 2 + 1] + sred[(64 + eb) * 8 + ejp * 2 + 1] + Gc.y;
            float hn0 = (1.0f - zv.x) * hv.x + zv.x * tanhf(s0);
            float hn1 = (1.0f - zv.y) * hv.y + zv.y * tanhf(s1);
            *(float2*)&g_h[eb * NU + j0] = make_float2(hn0, hn1);
            *(float2*)&out[((size_t)eb * NTT + t) * NU + j0] = make_float2(hn0, hn1);
            int comp = ((eb >> 3) & 1) | ((bx & 1) << 1);
            ((uint32_t*)&g_hF[((eb >> 4) * 64 + (bx >> 1)) * 32 + (((eb & 7) << 2) | ejp)])[comp]
                = pack2hf(hn0, hn1);
        }
        grid_bar();
    }
}

// ------------------------- launch -------------------------------------------
extern "C" void kernel_launch(void* const* d_in, const int* in_sizes, int n_in,
                              void* d_out, int out_size) {
    const float* all = (const float*)d_in[0];
    const float* h0  = (const float*)d_in[1];
    const float* Wr  = (const float*)d_in[2];
    const float* Ur  = (const float*)d_in[3];
    const float* Cr  = (const float*)d_in[4];
    const float* Wz  = (const float*)d_in[5];
    const float* Uz  = (const float*)d_in[6];
    const float* Cz  = (const float*)d_in[7];
    const float* Wc  = (const float*)d_in[8];
    const float* Uc  = (const float*)d_in[9];
    const float* Cc  = (const float*)d_in[10];
    float* out = (float*)d_out;

    pack_AF<<<16384, 256>>>(all);
    pack_WF<<<6144, 256>>>(Wr, Cr, Wz, Cz, Wc, Cc);
    pack_UrzF<<<2048, 256>>>(Ur, Uz);
    pack_UcF<<<1024, 256>>>(Uc);
    pack_h_init<<<256, 256>>>(h0);
    gemm_pre_f<<<dim3(24, 128), 256>>>();
    recurrent<<<NBLK, 256>>>(out);
}

// round 14
// speedup vs baseline: 2.7341x; 1.0014x over previous
#include <cuda_runtime.h>
#include <cuda_bf16.h>
#include <cuda_fp16.h>
#include <math.h>
#include <stdint.h>

#define NB 64
#define NTT 256
#define NU 1024
#define KX 2048
#define N3 3072
#define NBLK 128

// ------------------------- device scratch (no allocs allowed) ----------------
__device__ __align__(16) uint4 g_AF[(size_t)1024 * 128 * 32];   // A frag-major f16 (64MB)
__device__ __align__(16) uint2 g_WF[(size_t)384 * 128 * 32];    // W frag-major f16 (12.6MB)
__device__ __align__(16) float g_G[(size_t)NTT * NB * N3];
__device__ __align__(16) uint4 g_UrzF[256 * 64 * 32];           // frag-packed [U_r|U_z] f16 hi/lo
__device__ __align__(16) uint4 g_UcF[128 * 64 * 32];            // frag-packed U f16 hi/lo
__device__ __align__(16) uint4 g_hF[4 * 64 * 32];               // h as f16 A-fragments (128KB)
__device__ __align__(16) uint4 g_a2F[4 * 64 * 32];              // a2 as f16 A-fragments
__device__ __align__(16) float g_h[NB * NU];
__device__ __align__(16) float g_z[NB * NU];

// grid barrier state (monotonic generation -> safe across graph replays)
__device__ unsigned g_cnt = 0;
__device__ unsigned g_gen = 0;

__device__ __forceinline__ void grid_bar() {
    __syncthreads();
    if (threadIdx.x == 0) {
        unsigned gen = *((volatile unsigned*)&g_gen);
        __threadfence();
        if (atomicAdd(&g_cnt, 1u) == NBLK - 1u) {
            g_cnt = 0;
            __threadfence();
            atomicAdd(&g_gen, 1u);
        } else {
            unsigned spins = 0;
            while (*((volatile unsigned*)&g_gen) == gen) {
                if (++spins > 4096u) __nanosleep(40);
                if (spins > 4000000u) break;   // safety valve: never hang
            }
        }
        __threadfence();
    }
    __syncthreads();
}

// ------------------------- mma.sync helpers (sm_80+ ISA) ---------------------
#define MMA_F16(d, a0, a1, a2, a3, b0, b1) \
    asm volatile("mma.sync.aligned.m16n8k16.row.col.f32.f16.f16.f32 " \
                 "{%0,%1,%2,%3}, {%4,%5,%6,%7}, {%8,%9}, {%0,%1,%2,%3};" \
                 : "+f"((d)[0]), "+f"((d)[1]), "+f"((d)[2]), "+f"((d)[3]) \
                 : "r"(a0), "r"(a1), "r"(a2), "r"(a3), "r"(b0), "r"(b1))

static __device__ __forceinline__ uint32_t pack2hf(float x, float y) {
    __half2 v = {__float2half(x), __float2half(y)};
    return *(uint32_t*)&v;
}
static __device__ __forceinline__ uint32_t pack2lf(float x, float y) {
    float hx = __half2float(__float2half(x));
    float hy = __half2float(__float2half(y));
    __half2 v = {__float2half(x - hx), __float2half(y - hy)};
    return *(uint32_t*)&v;
}
static __device__ __forceinline__ float hsig(float x) {
    return fminf(fmaxf(0.2f * x + 0.5f, 0.0f), 1.0f);
}

// ------------------------- packing / init -----------------------------------
__global__ void pack_AF(const float* __restrict__ all) {
    int fid = blockIdx.x * blockDim.x + threadIdx.x;   // 4194304
    int lane = fid & 31, kc = (fid >> 5) & 127, m16t = fid >> 12;
    int row = m16t * 16 + (lane >> 2);
    int col = kc * 16 + (lane & 3) * 2;
    const float* p = all + (size_t)row * KX + col;
    g_AF[fid] = make_uint4(pack2hf(p[0], p[1]),
                           pack2hf(p[8 * KX], p[8 * KX + 1]),
                           pack2hf(p[8], p[9]),
                           pack2hf(p[8 * KX + 8], p[8 * KX + 9]));
}

__global__ void pack_WF(const float* __restrict__ Wr, const float* __restrict__ Cr,
                        const float* __restrict__ Wz, const float* __restrict__ Cz,
                        const float* __restrict__ Wc, const float* __restrict__ Cc) {
    int fid = blockIdx.x * blockDim.x + threadIdx.x;   // 1572864
    int lane = fid & 31, kc = (fid >> 5) & 127, n8t = fid >> 12;
    int n = n8t * 8 + (lane >> 2);
    int k0 = kc * 16 + (lane & 3) * 2;
    int sel = n >> 10, j = n & 1023;
    const float* C = (sel == 0) ? Cr : (sel == 1) ? Cz : Cc;
    const float* W = (sel == 0) ? Wr : (sel == 1) ? Wz : Wc;
    auto wat = [&](int k) -> float {
        return (k < 1024) ? C[k * NU + j] : W[(k - 1024) * NU + j];
    };
    g_WF[fid] = make_uint2(pack2hf(wat(k0), wat(k0 + 1)),
                           pack2hf(wat(k0 + 8), wat(k0 + 9)));
}

__global__ void pack_UrzF(const float* __restrict__ Ur, const float* __restrict__ Uz) {
    int fid = blockIdx.x * blockDim.x + threadIdx.x;   // 524288
    int nt = fid >> 11, kc = (fid >> 5) & 63, lane = fid & 31;
    int n = nt * 8 + (lane >> 2);
    int k0 = kc * 16 + (lane & 3) * 2;
    const float* src = (n < 1024) ? Ur : Uz;
    int nn = n & 1023;
    float v00 = src[(k0 + 0) * NU + nn], v01 = src[(k0 + 1) * NU + nn];
    float v10 = src[(k0 + 8) * NU + nn], v11 = src[(k0 + 9) * NU + nn];
    g_UrzF[fid] = make_uint4(pack2hf(v00, v01), pack2hf(v10, v11),
                             pack2lf(v00, v01), pack2lf(v10, v11));
}

__global__ void pack_UcF(const float* __restrict__ Uc) {
    int fid = blockIdx.x * blockDim.x + threadIdx.x;   // 262144
    int nt = fid >> 11, kc = (fid >> 5) & 63, lane = fid & 31;
    int n = nt * 8 + (lane >> 2);
    int k0 = kc * 16 + (lane & 3) * 2;
    float v00 = Uc[(k0 + 0) * NU + n], v01 = Uc[(k0 + 1) * NU + n];
    float v10 = Uc[(k0 + 8) * NU + n], v11 = Uc[(k0 + 9) * NU + n];
    g_UcF[fid] = make_uint4(pack2hf(v00, v01), pack2hf(v10, v11),
                            pack2lf(v00, v01), pack2lf(v10, v11));
}

__global__ void pack_h_init(const float* __restrict__ h0) {
    int i = blockIdx.x * blockDim.x + threadIdx.x;     // 65536
    if (i < NB * NU) g_h[i] = h0[i];
    if (i < 4 * 64 * 32) {                              // h fragments
        int lane = i & 31, kc = (i >> 5) & 63, m16t = i >> 11;
        int r0 = m16t * 16 + (lane >> 2);
        int c0 = kc * 16 + (lane & 3) * 2;
        g_hF[i] = make_uint4(
            pack2hf(h0[r0 * NU + c0],           h0[r0 * NU + c0 + 1]),
            pack2hf(h0[(r0 + 8) * NU + c0],     h0[(r0 + 8) * NU + c0 + 1]),
            pack2hf(h0[r0 * NU + c0 + 8],       h0[r0 * NU + c0 + 9]),
            pack2hf(h0[(r0 + 8) * NU + c0 + 8], h0[(r0 + 8) * NU + c0 + 9]));
    }
}

// ------------------------- frag-direct precompute GEMM (single f16) ----------
__global__ __launch_bounds__(256) void gemm_pre_f() {
    const int tid = threadIdx.x;
    const int wid = tid >> 5, lane = tid & 31;
    const int wm = wid >> 2, wn = wid & 3;
    const int bn = blockIdx.x, bm = blockIdx.y;

    float acc[4][4][4];
#pragma unroll
    for (int i = 0; i < 4; i++)
#pragma unroll
        for (int j = 0; j < 4; j++)
#pragma unroll
            for (int k = 0; k < 4; k++) acc[i][j][k] = 0.0f;

    const uint4* ap = g_AF + ((size_t)(bm * 8 + wm * 4) * 128) * 32 + lane;
    const uint2* bp = g_WF + ((size_t)(bn * 16 + wn * 4) * 128) * 32 + lane;

    for (int kc = 0; kc < 128; kc++) {
        uint4 af[4];
        uint2 bf[4];
#pragma unroll
        for (int mi = 0; mi < 4; mi++) af[mi] = ap[(size_t)(mi * 128 + kc) * 32];
#pragma unroll
        for (int ni = 0; ni < 4; ni++) bf[ni] = bp[(size_t)(ni * 128 + kc) * 32];
#pragma unroll
        for (int mi = 0; mi < 4; mi++)
#pragma unroll
            for (int ni = 0; ni < 4; ni++)
                MMA_F16(acc[mi][ni], af[mi].x, af[mi].y, af[mi].z, af[mi].w,
                        bf[ni].x, bf[ni].y);
    }

#pragma unroll
    for (int mi = 0; mi < 4; mi++) {
        int mA = bm * 128 + wm * 64 + mi * 16 + (lane >> 2);
        int mB = mA + 8;
        int bA = mA >> 8, tA = mA & 255;
        int bB = mB >> 8, tB = mB & 255;
        float* oA = g_G + (size_t)(tA * NB + bA) * N3;
        float* oB = g_G + (size_t)(tB * NB + bB) * N3;
        int colb = bn * 128 + wn * 32 + (lane & 3) * 2;
#pragma unroll
        for (int ni = 0; ni < 4; ni++) {
            int c = colb + ni * 8;
            *(float2*)(oA + c) = make_float2(acc[mi][ni][0], acc[mi][ni][1]);
            *(float2*)(oB + c) = make_float2(acc[mi][ni][2], acc[mi][ni][3]);
        }
    }
}

// ------------------------- persistent recurrent kernel -----------------------
// U-fragments staged ONCE into smem (96KB); G/h loads prefetched across
// barriers. Math identical to R13 (rel_err canary).
__global__ __launch_bounds__(256, 1) void recurrent(float* __restrict__ out) {
    extern __shared__ __align__(16) uint4 dsm[];
    uint4* sU = dsm;                                   // [0,2048): b0, [2048,4096): b1, [4096,6144): uc
    float* sred = (float*)(dsm + 6144);                // 8KB reduce buffer
    const int bx = blockIdx.x;
    const int tid = threadIdx.x;
    const int wid = tid >> 5, lane = tid & 31;
    const int wm = wid >> 1, ws = wid & 1;
    const int erow = wm * 16 + (lane >> 2);
    const int ecol2 = (lane & 3) * 2;
    const int eb = tid >> 2, ejp = tid & 3;            // phase B final mapping

    // ---- stage U fragments into smem (once) ----
    {
        const uint4* u0 = g_UrzF + (size_t)(bx * 2 + 0) * 2048;
        const uint4* u1 = g_UrzF + (size_t)(bx * 2 + 1) * 2048;
        const uint4* uc = g_UcF + (size_t)bx * 2048;
#pragma unroll
        for (int i = 0; i < 8; i++) {
            int idx = i * 256 + tid;
            sU[idx] = u0[idx];
            sU[2048 + idx] = u1[idx];
            sU[4096 + idx] = uc[idx];
        }
    }
    __syncthreads();

    const int colg = bx * 16 + ws * 8 + ecol2;
    const int j0 = bx * 8 + ejp * 2;
    float2 G0 = *(const float2*)&g_G[((size_t)0 * NB + erow) * N3 + colg];
    float2 G1 = *(const float2*)&g_G[((size_t)0 * NB + erow + 8) * N3 + colg];

    for (int t = 0; t < NTT; t++) {
        // ===== phase A: h @ [U_r|U_z], K-split over ws, fused act_rz =========
        float2 Gc, hv;
        {
            const uint4* afr = g_hF + (wm * 64) * 32 + lane;
            float2 h0v = make_float2(0.f, 0.f), h1v = make_float2(0.f, 0.f);
            if (bx < 64) {
                h0v = __ldcg((const float2*)&g_h[erow * NU + colg]);
                h1v = __ldcg((const float2*)&g_h[(erow + 8) * NU + colg]);
            }
            float a0h[4] = {0.f, 0.f, 0.f, 0.f}, a0l[4] = {0.f, 0.f, 0.f, 0.f};
            float a1h[4] = {0.f, 0.f, 0.f, 0.f}, a1l[4] = {0.f, 0.f, 0.f, 0.f};
#pragma unroll 4
            for (int kc = 0; kc < 32; kc++) {
                int kk = ws * 32 + kc;
                uint4 av = __ldcg(&afr[kk * 32]);
                uint4 v0 = sU[kk * 32 + lane];
                uint4 v1 = sU[2048 + kk * 32 + lane];
                MMA_F16(a0h, av.x, av.y, av.z, av.w, v0.x, v0.y);
                MMA_F16(a0l, av.x, av.y, av.z, av.w, v0.z, v0.w);
                MMA_F16(a1h, av.x, av.y, av.z, av.w, v1.x, v1.y);
                MMA_F16(a1l, av.x, av.y, av.z, av.w, v1.z, v1.w);
            }
            *(float4*)&sred[((wm * 2 + 0) * 2 + ws) * 128 + lane * 4] =
                make_float4(a0h[0] + a0l[0], a0h[1] + a0l[1],
                            a0h[2] + a0l[2], a0h[3] + a0l[3]);
            *(float4*)&sred[((wm * 2 + 1) * 2 + ws) * 128 + lane * 4] =
                make_float4(a1h[0] + a1l[0], a1h[1] + a1l[1],
                            a1h[2] + a1l[2], a1h[3] + a1l[3]);
            __syncthreads();
            float4 p0 = *(const float4*)&sred[((wm * 2 + ws) * 2 + 0) * 128 + lane * 4];
            float4 p1 = *(const float4*)&sred[((wm * 2 + ws) * 2 + 1) * 128 + lane * 4];
            float s00 = p0.x + p1.x + G0.x, s01 = p0.y + p1.y + G0.y;
            float s10 = p0.z + p1.z + G1.x, s11 = p0.w + p1.w + G1.y;
            if (bx < 64) {                              // r gate -> a2 frags
                float a0 = h0v.x * hsig(s00), a1 = h0v.y * hsig(s01);
                float a2v = h1v.x * hsig(s10), a3v = h1v.y * hsig(s11);
                uint2* dst = (uint2*)&g_a2F[(wm * 64 + bx) * 32 + lane];
                dst[ws] = make_uint2(pack2hf(a0, a1), pack2hf(a2v, a3v));
            } else {                                    // z gate
                int j = colg - 1024;
                *(float2*)&g_z[erow * NU + j] = make_float2(hsig(s00), hsig(s01));
                *(float2*)&g_z[(erow + 8) * NU + j] = make_float2(hsig(s10), hsig(s11));
            }
            // prefetch phase-B inputs that don't depend on other CTAs' phase A
            Gc = *(const float2*)&g_G[((size_t)t * NB + eb) * N3 + 2048 + j0];
            hv = __ldcg((const float2*)&g_h[eb * NU + j0]);
        }
        grid_bar();
        // ===== phase B: (h*r) @ U, cols bx*8..+8, fused act_h ================
        {
            const uint4* afr = g_a2F + (wm * 64) * 32 + lane;
            float2 zv = __ldcg((const float2*)&g_z[eb * NU + j0]);
            float ach[4] = {0.f, 0.f, 0.f, 0.f}, acl[4] = {0.f, 0.f, 0.f, 0.f};
#pragma unroll 8
            for (int kc = 0; kc < 32; kc++) {
                int kk = ws * 32 + kc;
                uint4 av = __ldcg(&afr[kk * 32]);
                uint4 bv = sU[4096 + kk * 32 + lane];
                MMA_F16(ach, av.x, av.y, av.z, av.w, bv.x, bv.y);
                MMA_F16(acl, av.x, av.y, av.z, av.w, bv.z, bv.w);
            }
            *(float2*)&sred[(ws * 64 + erow) * 8 + ecol2] =
                make_float2(ach[0] + acl[0], ach[1] + acl[1]);
            *(float2*)&sred[(ws * 64 + erow + 8) * 8 + ecol2] =
                make_float2(ach[2] + acl[2], ach[3] + acl[3]);
            __syncthreads();
            float s0 = sred[eb * 8 + ejp * 2]     + sred[(64 + eb) * 8 + ejp * 2]     + Gc.x;
            float s1 = sred[eb * 8 + ejp * 2 + 1] + sred[(64 + eb) * 8 + ejp * 2 + 1] + Gc.y;
            float hn0 = (1.0f - zv.x) * hv.x + zv.x * tanhf(s0);
            float hn1 = (1.0f - zv.y) * hv.y + zv.y * tanhf(s1);
            *(float2*)&g_h[eb * NU + j0] = make_float2(hn0, hn1);
            *(float2*)&out[((size_t)eb * NTT + t) * NU + j0] = make_float2(hn0, hn1);
            int comp = ((eb >> 3) & 1) | ((bx & 1) << 1);
            ((uint32_t*)&g_hF[((eb >> 4) * 64 + (bx >> 1)) * 32 + (((eb & 7) << 2) | ejp)])[comp]
                = pack2hf(hn0, hn1);
            // prefetch next step's gate biases
            int tn = (t + 1 < NTT) ? t + 1 : t;
            G0 = *(const float2*)&g_G[((size_t)tn * NB + erow) * N3 + colg];
            G1 = *(const float2*)&g_G[((size_t)tn * NB + erow + 8) * N3 + colg];
        }
        grid_bar();
    }
}

// ------------------------- launch -------------------------------------------
#define REC_SMEM (6144 * 16 + 8192)

extern "C" void kernel_launch(void* const* d_in, const int* in_sizes, int n_in,
                              void* d_out, int out_size) {
    const float* all = (const float*)d_in[0];
    const float* h0  = (const float*)d_in[1];
    const float* Wr  = (const float*)d_in[2];
    const float* Ur  = (const float*)d_in[3];
    const float* Cr  = (const float*)d_in[4];
    const float* Wz  = (const float*)d_in[5];
    const float* Uz  = (const float*)d_in[6];
    const float* Cz  = (const float*)d_in[7];
    const float* Wc  = (const float*)d_in[8];
    const float* Uc  = (const float*)d_in[9];
    const float* Cc  = (const float*)d_in[10];
    float* out = (float*)d_out;

    static int smem_set = 0;
    if (!smem_set) {
        cudaFuncSetAttribute(recurrent, cudaFuncAttributeMaxDynamicSharedMemorySize, REC_SMEM);
        smem_set = 1;
    }

    pack_AF<<<16384, 256>>>(all);
    pack_WF<<<6144, 256>>>(Wr, Cr, Wz, Cz, Wc, Cc);
    pack_UrzF<<<2048, 256>>>(Ur, Uz);
    pack_UcF<<<1024, 256>>>(Uc);
    pack_h_init<<<256, 256>>>(h0);
    gemm_pre_f<<<dim3(24, 128), 256>>>();
    recurrent<<<NBLK, 256, REC_SMEM>>>(out);
}